// round 13
// baseline (speedup 1.0000x reference)
#include <cuda_runtime.h>
#include <cuda_bf16.h>
#include <math.h>
#include <stdint.h>

// Problem constants: B=1, T=2048, D=1024, H=16, HD=64
#define T_SEQ 2048
#define D_MOD 1024
#define NH    16
#define HDIM  64

// Scratch (allocation-free rule: __device__ globals)
__device__ __nv_bfloat16 g_Khi[4096 * 1024];   // K natural [s][1024]
__device__ __nv_bfloat16 g_Klo[4096 * 1024];
__device__ __nv_bfloat16 g_VThi[1024 * 4096];  // V transposed [d][4096]
__device__ __nv_bfloat16 g_VTlo[1024 * 4096];
__device__ __nv_bfloat16 g_Qhi[2048 * 1024];   // Q natural [q][1024]
__device__ __nv_bfloat16 g_Qlo[2048 * 1024];
__device__ float g_Y[T_SEQ * D_MOD];           // attention output (fp32, proj input)
// split-KV partials
__device__ float g_Op[2][NH][16][128][64];     // unnormalized partial O
__device__ float g_ml[2][NH][16][2][128];      // [0]=m, [1]=l per row

// ---------------------------------------------------------------------------
// helpers
// ---------------------------------------------------------------------------
__device__ __forceinline__ float to_tf32(float f) {
    uint32_t u;
    asm("cvt.rna.tf32.f32 %0, %1;" : "=r"(u) : "f"(f));
    return __uint_as_float(u);
}

__device__ __forceinline__ void mma_tf32(float* c,
    uint32_t a0, uint32_t a1, uint32_t a2, uint32_t a3,
    uint32_t b0, uint32_t b1)
{
    asm volatile(
        "mma.sync.aligned.m16n8k8.row.col.f32.tf32.tf32.f32 "
        "{%0,%1,%2,%3}, {%4,%5,%6,%7}, {%8,%9}, {%0,%1,%2,%3};\n"
        : "+f"(c[0]), "+f"(c[1]), "+f"(c[2]), "+f"(c[3])
        : "r"(a0), "r"(a1), "r"(a2), "r"(a3), "r"(b0), "r"(b1));
}

__device__ __forceinline__ void mma_bf16(float* c,
    uint32_t a0, uint32_t a1, uint32_t a2, uint32_t a3,
    uint32_t b0, uint32_t b1)
{
    asm volatile(
        "mma.sync.aligned.m16n8k16.row.col.f32.bf16.bf16.f32 "
        "{%0,%1,%2,%3}, {%4,%5,%6,%7}, {%8,%9}, {%0,%1,%2,%3};\n"
        : "+f"(c[0]), "+f"(c[1]), "+f"(c[2]), "+f"(c[3])
        : "r"(a0), "r"(a1), "r"(a2), "r"(a3), "r"(b0), "r"(b1));
}

__device__ __forceinline__ void bsplit(float x, __nv_bfloat16& h, __nv_bfloat16& l) {
    h = __float2bfloat16(x);
    l = __float2bfloat16(x - __bfloat162float(h));
}

__device__ __forceinline__ uint32_t bpack(__nv_bfloat16 lo, __nv_bfloat16 hi) {
    __nv_bfloat162 p = __halves2bfloat162(lo, hi);   // lo -> bits[0:16)
    return *(uint32_t*)&p;
}

__device__ __forceinline__ void cp16(uint32_t dst, const void* src) {
    asm volatile("cp.async.cg.shared.global [%0], [%1], 16;\n" :: "r"(dst), "l"(src));
}
#define CP_COMMIT() asm volatile("cp.async.commit_group;\n" ::: "memory")
#define CP_WAIT1()  asm volatile("cp.async.wait_group 1;\n" ::: "memory")

__device__ __forceinline__ uint32_t sma(const void* p) {
    return (uint32_t)__cvta_generic_to_shared(p);
}

// ---------------------------------------------------------------------------
// GEMM core v2: fragment-order shared memory.
// A blocks: bid = (wm*4+fm)*4+ks, ABLK=136 floats; element (m,k):
//   off = bid*ABLK + g*16 + t*4 + half*2 + mrow   (g=m&7, t=k&3, half=(k>>2)&1,
//   mrow=(m>>3)&1) -> consumer LDS.128 at bid*ABLK + (g*4+t)*4 gives a0..a3.
// B blocks: bid = (wn*4+fn)*4+ks, BBLK=66 floats; element (k,n):
//   off = bid*BBLK + g*8 + t*2 + half -> consumer LDS.64 gives b0,b1.
// Both consumer loads conflict-free per access phase.
// ---------------------------------------------------------------------------
#define ABLK 136
#define BBLK 66
#define GEMM_SMEM_FLOATS (32 * ABLK + 64 * BBLK)   // 8576 floats = 34304 B

__device__ __forceinline__ void gemm_core(
    const float* __restrict__ A, const float* __restrict__ W,
    int N, int m0, int n0, int tid,
    float* __restrict__ As, float* __restrict__ Bs, float acc[4][4][4])
{
    const int wid  = tid >> 5;
    const int lane = tid & 31;
    const int g    = lane >> 2;
    const int t    = lane & 3;
    const int warp_m = wid >> 2;
    const int warp_n = wid & 3;

    // loader coordinates + precomputed smem offsets
    int aoff[4], boff[4];
    int ar_[4], ac_[4], br_[4], bc_[4];
#pragma unroll
    for (int i = 0; i < 4; i++) {
        int lin = tid + (i << 8);
        int ar = lin >> 3;             // 0..127
        int ac = (lin & 7) << 2;       // 0..28
        int wm = ar >> 6, fm = (ar >> 4) & 3, ga = ar & 7, mrow = (ar >> 3) & 1;
        int ksa = ac >> 3, halfa = (ac >> 2) & 1;
        aoff[i] = ((wm * 4 + fm) * 4 + ksa) * ABLK + ga * 16 + halfa * 2 + mrow;
        ar_[i] = ar; ac_[i] = ac;
        int br = lin >> 5;             // 0..31
        int bc = (lin & 31) << 2;      // 0..124
        int ksb = br >> 3, halfb = (br >> 2) & 1, tb = br & 3;
        int wn = bc >> 5, fn = (bc >> 3) & 3, gb = bc & 7;
        boff[i] = ((wn * 4 + fn) * 4 + ksb) * BBLK + gb * 8 + tb * 2 + halfb;
        br_[i] = br; bc_[i] = bc;
    }

    float4 pa[4], pb[4];
#pragma unroll
    for (int i = 0; i < 4; i++) {
        pa[i] = *(const float4*)&A[(size_t)(m0 + ar_[i]) * 1024 + ac_[i]];
        pb[i] = *(const float4*)&W[(size_t)br_[i] * N + n0 + bc_[i]];
    }

    for (int kt = 0; kt < 32; kt++) {
        // store prefetched tile (tf32-rounded) into fragment-order smem
#pragma unroll
        for (int i = 0; i < 4; i++) {
            float* ad = &As[aoff[i]];
            ad[0]  = to_tf32(pa[i].x);   // t = 0..3 -> stride 4 floats
            ad[4]  = to_tf32(pa[i].y);
            ad[8]  = to_tf32(pa[i].z);
            ad[12] = to_tf32(pa[i].w);
            float* bd = &Bs[boff[i]];
            bd[0]  = to_tf32(pb[i].x);   // g increments -> stride 8 floats
            bd[8]  = to_tf32(pb[i].y);
            bd[16] = to_tf32(pb[i].z);
            bd[24] = to_tf32(pb[i].w);
        }
        __syncthreads();

        if (kt < 31) {
            int k0 = (kt + 1) << 5;
#pragma unroll
            for (int i = 0; i < 4; i++) {
                pa[i] = *(const float4*)&A[(size_t)(m0 + ar_[i]) * 1024 + k0 + ac_[i]];
                pb[i] = *(const float4*)&W[(size_t)(k0 + br_[i]) * N + n0 + bc_[i]];
            }
        }

#pragma unroll
        for (int ks = 0; ks < 4; ks++) {
            float2 bf[4];
#pragma unroll
            for (int fn = 0; fn < 4; fn++)
                bf[fn] = *(float2*)&Bs[((warp_n * 4 + fn) * 4 + ks) * BBLK + g * 8 + t * 2];
#pragma unroll
            for (int fm = 0; fm < 4; fm++) {
                float4 af = *(float4*)&As[((warp_m * 4 + fm) * 4 + ks) * ABLK + (g * 4 + t) * 4];
                uint32_t a0 = __float_as_uint(af.x);
                uint32_t a1 = __float_as_uint(af.y);
                uint32_t a2 = __float_as_uint(af.z);
                uint32_t a3 = __float_as_uint(af.w);
#pragma unroll
                for (int fn = 0; fn < 4; fn++)
                    mma_tf32(acc[fm][fn], a0, a1, a2, a3,
                             __float_as_uint(bf[fn].x), __float_as_uint(bf[fn].y));
            }
        }
        __syncthreads();
    }
}

// ---------------------------------------------------------------------------
// Merged QKV projection GEMM: grid (40, 16).
//   bx in [0,16):  l  @ W_attn_l -> K rows 0:2048 / VT cols (rowoff 0)
//   bx in [16,32): x  @ W_attn_c -> K rows 2048:4096 / VT (rowoff 2048)
//   bx in [32,40): x  @ W_q      -> Q (natural bf16 hi/lo)
// ---------------------------------------------------------------------------
__global__ __launch_bounds__(256) void gemm_qkv_kernel(
    const float* __restrict__ lin_, const float* __restrict__ xin_,
    const float* __restrict__ Wl, const float* __restrict__ bl,
    const float* __restrict__ Wc, const float* __restrict__ bc2,
    const float* __restrict__ Wq, const float* __restrict__ bq,
    __nv_bfloat16* __restrict__ Khi, __nv_bfloat16* __restrict__ Klo,
    __nv_bfloat16* __restrict__ VThi, __nv_bfloat16* __restrict__ VTlo,
    __nv_bfloat16* __restrict__ Qhi, __nv_bfloat16* __restrict__ Qlo)
{
    __shared__ float smem[GEMM_SMEM_FLOATS];
    float* As = smem;
    float* Bs = smem + 32 * ABLK;

    const int bx = blockIdx.x;
    const float *A, *W, *bias;
    int N, rowoff, n0;
    bool qmode;
    if (bx < 16)      { A = lin_; W = Wl; bias = bl;  N = 2048; rowoff = 0;    n0 = bx << 7;        qmode = false; }
    else if (bx < 32) { A = xin_; W = Wc; bias = bc2; N = 2048; rowoff = 2048; n0 = (bx - 16) << 7; qmode = false; }
    else              { A = xin_; W = Wq; bias = bq;  N = 1024; rowoff = 0;    n0 = (bx - 32) << 7; qmode = true;  }
    const int m0 = blockIdx.y << 7;

    float acc[4][4][4];
#pragma unroll
    for (int fm = 0; fm < 4; fm++)
#pragma unroll
        for (int fn = 0; fn < 4; fn++)
#pragma unroll
            for (int e = 0; e < 4; e++) acc[fm][fn][e] = 0.0f;

    gemm_core(A, W, N, m0, n0, threadIdx.x, As, Bs, acc);

    const int tid  = threadIdx.x;
    const int wid  = tid >> 5;
    const int lane = tid & 31;
    const int g    = lane >> 2;
    const int t    = lane & 3;
    const int warp_m = wid >> 2;
    const int warp_n = wid & 3;

#pragma unroll
    for (int fm = 0; fm < 4; fm++) {
        int row = m0 + warp_m * 64 + fm * 16 + g;
        int srow = rowoff + row;
#pragma unroll
        for (int fn = 0; fn < 4; fn++) {
            int col = n0 + warp_n * 32 + fn * 8 + 2 * t;
            float bx0 = bias[col], by0 = bias[col + 1];
            float v0x = acc[fm][fn][0] + bx0, v0y = acc[fm][fn][1] + by0;
            float v1x = acc[fm][fn][2] + bx0, v1y = acc[fm][fn][3] + by0;
            __nv_bfloat16 h0, l0, h1, l1, h2, l2, h3, l3;
            bsplit(v0x, h0, l0); bsplit(v0y, h1, l1);
            bsplit(v1x, h2, l2); bsplit(v1y, h3, l3);
            if (qmode) {
                *(uint32_t*)&Qhi[(size_t)srow * 1024 + col] = bpack(h0, h1);
                *(uint32_t*)&Qlo[(size_t)srow * 1024 + col] = bpack(l0, l1);
                *(uint32_t*)&Qhi[(size_t)(srow + 8) * 1024 + col] = bpack(h2, h3);
                *(uint32_t*)&Qlo[(size_t)(srow + 8) * 1024 + col] = bpack(l2, l3);
            } else if (col < 1024) {
                *(uint32_t*)&Khi[(size_t)srow * 1024 + col] = bpack(h0, h1);
                *(uint32_t*)&Klo[(size_t)srow * 1024 + col] = bpack(l0, l1);
                *(uint32_t*)&Khi[(size_t)(srow + 8) * 1024 + col] = bpack(h2, h3);
                *(uint32_t*)&Klo[(size_t)(srow + 8) * 1024 + col] = bpack(l2, l3);
            } else {
                int d0 = col - 1024;
                VThi[(size_t)d0 * 4096 + srow] = h0;        VTlo[(size_t)d0 * 4096 + srow] = l0;
                VThi[(size_t)(d0 + 1) * 4096 + srow] = h1;  VTlo[(size_t)(d0 + 1) * 4096 + srow] = l1;
                VThi[(size_t)d0 * 4096 + srow + 8] = h2;    VTlo[(size_t)d0 * 4096 + srow + 8] = l2;
                VThi[(size_t)(d0 + 1) * 4096 + srow + 8] = h3; VTlo[(size_t)(d0 + 1) * 4096 + srow + 8] = l3;
            }
        }
    }
}

// Output projection GEMM (fp32 epilogue), same core.
__global__ __launch_bounds__(256) void gemm_proj_kernel(
    const float* __restrict__ A, const float* __restrict__ W,
    const float* __restrict__ bias, float* __restrict__ outf)
{
    __shared__ float smem[GEMM_SMEM_FLOATS];
    float* As = smem;
    float* Bs = smem + 32 * ABLK;

    const int n0 = blockIdx.x << 7;
    const int m0 = blockIdx.y << 7;

    float acc[4][4][4];
#pragma unroll
    for (int fm = 0; fm < 4; fm++)
#pragma unroll
        for (int fn = 0; fn < 4; fn++)
#pragma unroll
            for (int e = 0; e < 4; e++) acc[fm][fn][e] = 0.0f;

    gemm_core(A, W, 1024, m0, n0, threadIdx.x, As, Bs, acc);

    const int tid  = threadIdx.x;
    const int wid  = tid >> 5;
    const int lane = tid & 31;
    const int g    = lane >> 2;
    const int t    = lane & 3;
    const int warp_m = wid >> 2;
    const int warp_n = wid & 3;

#pragma unroll
    for (int fm = 0; fm < 4; fm++) {
        int row = m0 + warp_m * 64 + fm * 16 + g;
#pragma unroll
        for (int fn = 0; fn < 4; fn++) {
            int col = n0 + warp_n * 32 + fn * 8 + 2 * t;
            float bx0 = bias[col], by0 = bias[col + 1];
            *(float2*)&outf[(size_t)row * 1024 + col] =
                make_float2(acc[fm][fn][0] + bx0, acc[fm][fn][1] + by0);
            *(float2*)&outf[(size_t)(row + 8) * 1024 + col] =
                make_float2(acc[fm][fn][2] + bx0, acc[fm][fn][3] + by0);
        }
    }
}

// ---------------------------------------------------------------------------
// Tensor-core flash attention v5 (unchanged, measured-good R12): split-KV.
// ---------------------------------------------------------------------------
#define BSTR 72   // bf16 row stride (144 B = 36 words; bank = 4*row + t)

__device__ __forceinline__ void load_tile_async(
    int tid, int col0, int s0,
    const __nv_bfloat16* __restrict__ Khi_g, const __nv_bfloat16* __restrict__ Klo_g,
    const __nv_bfloat16* __restrict__ VThi_g, const __nv_bfloat16* __restrict__ VTlo_g,
    __nv_bfloat16* Kh, __nv_bfloat16* Kl, __nv_bfloat16* Vh, __nv_bfloat16* Vl)
{
#pragma unroll
    for (int c = 0; c < 2; c++) {
        int idx = (tid << 1) + c;          // 0..511
        int j = idx >> 3;                  // 0..63
        int ch = (idx & 7) << 3;           // bf16 offset, 16B chunks
        cp16(sma(Kh + j * BSTR + ch), Khi_g + (size_t)(s0 + j) * 1024 + col0 + ch);
        cp16(sma(Kl + j * BSTR + ch), Klo_g + (size_t)(s0 + j) * 1024 + col0 + ch);
        cp16(sma(Vh + j * BSTR + ch), VThi_g + (size_t)(col0 + j) * 4096 + s0 + ch);
        cp16(sma(Vl + j * BSTR + ch), VTlo_g + (size_t)(col0 + j) * 4096 + s0 + ch);
    }
}

__global__ __launch_bounds__(256, 2) void attn_mma_kernel(
    const __nv_bfloat16* __restrict__ Qhi_g, const __nv_bfloat16* __restrict__ Qlo_g,
    const __nv_bfloat16* __restrict__ Khi_g, const __nv_bfloat16* __restrict__ Klo_g,
    const __nv_bfloat16* __restrict__ VThi_g, const __nv_bfloat16* __restrict__ VTlo_g)
{
    extern __shared__ char smraw[];
    __nv_bfloat16* Qhi_s = (__nv_bfloat16*)smraw;     // [128][BSTR]
    __nv_bfloat16* Qlo_s = Qhi_s + 128 * BSTR;
    __nv_bfloat16* Kh_s  = Qlo_s + 128 * BSTR;        // [2][64][BSTR]
    __nv_bfloat16* Kl_s  = Kh_s + 2 * 64 * BSTR;
    __nv_bfloat16* Vh_s  = Kl_s + 2 * 64 * BSTR;
    __nv_bfloat16* Vl_s  = Vh_s + 2 * 64 * BSTR;

    const int tid  = threadIdx.x;
    const int wid  = tid >> 5;
    const int lane = tid & 31;
    const int g    = lane >> 2;   // 0..7
    const int t    = lane & 3;    // 0..3

    const int bx = blockIdx.x;               // 0..31, largest work first
    const int qb = 15 - (bx >> 1);
    const int split = bx & 1;
    const int h  = blockIdx.y;
    const int q0 = qb << 7;
    const int col0 = h * HDIM;

    const int nt_total = 2 * qb + 34;        // 34..64
    const int nt0 = nt_total >> 1;           // 17..32
    const int tb = split ? nt0 : 0;
    const int te = split ? nt_total : nt0;

    const int row0 = wid * 16 + g;

    // ---- prologue: async-load Q + tiles tb, tb+1 ----
#pragma unroll
    for (int c = 0; c < 4; c++) {
        int idx = (tid << 2) + c;          // 0..1023
        int r = idx >> 3;
        int ch = (idx & 7) << 3;
        cp16(sma(Qhi_s + r * BSTR + ch), Qhi_g + (size_t)(q0 + r) * 1024 + col0 + ch);
        cp16(sma(Qlo_s + r * BSTR + ch), Qlo_g + (size_t)(q0 + r) * 1024 + col0 + ch);
    }
    load_tile_async(tid, col0, tb << 6, Khi_g, Klo_g, VThi_g, VTlo_g,
                    Kh_s, Kl_s, Vh_s, Vl_s);
    CP_COMMIT();
    load_tile_async(tid, col0, (tb + 1) << 6, Khi_g, Klo_g, VThi_g, VTlo_g,
                    Kh_s + 64 * BSTR, Kl_s + 64 * BSTR, Vh_s + 64 * BSTR, Vl_s + 64 * BSTR);
    CP_COMMIT();

    float O[8][4];
#pragma unroll
    for (int fn = 0; fn < 8; fn++)
#pragma unroll
        for (int e = 0; e < 4; e++) O[fn][e] = 0.0f;
    float m0 = -INFINITY, m1 = -INFINITY, l0 = 0.0f, l1 = 0.0f;

    for (int tt = tb; tt < te; tt++) {
        int s0 = tt << 6;
        int p = (tt - tb) & 1;
        const __nv_bfloat16* Kh = Kh_s + p * 64 * BSTR;
        const __nv_bfloat16* Kl = Kl_s + p * 64 * BSTR;
        const __nv_bfloat16* Vh = Vh_s + p * 64 * BSTR;
        const __nv_bfloat16* Vl = Vl_s + p * 64 * BSTR;

        CP_WAIT1();
        __syncthreads();

        // ---- S = Q K^T via 3-mma bf16 split (lo*lo dropped) ----
        float sacc[8][4];
#pragma unroll
        for (int fn = 0; fn < 8; fn++)
#pragma unroll
            for (int e = 0; e < 4; e++) sacc[fn][e] = 0.0f;

#pragma unroll
        for (int ks = 0; ks < 4; ks++) {
            int k0 = ks << 4;
            uint32_t ah0 = *(uint32_t*)&Qhi_s[row0 * BSTR + k0 + 2 * t];
            uint32_t ah1 = *(uint32_t*)&Qhi_s[(row0 + 8) * BSTR + k0 + 2 * t];
            uint32_t ah2 = *(uint32_t*)&Qhi_s[row0 * BSTR + k0 + 2 * t + 8];
            uint32_t ah3 = *(uint32_t*)&Qhi_s[(row0 + 8) * BSTR + k0 + 2 * t + 8];
            uint32_t al0 = *(uint32_t*)&Qlo_s[row0 * BSTR + k0 + 2 * t];
            uint32_t al1 = *(uint32_t*)&Qlo_s[(row0 + 8) * BSTR + k0 + 2 * t];
            uint32_t al2 = *(uint32_t*)&Qlo_s[row0 * BSTR + k0 + 2 * t + 8];
            uint32_t al3 = *(uint32_t*)&Qlo_s[(row0 + 8) * BSTR + k0 + 2 * t + 8];
#pragma unroll
            for (int fn = 0; fn < 8; fn++) {
                int key = fn * 8 + g;
                uint32_t bh0 = *(uint32_t*)&Kh[key * BSTR + k0 + 2 * t];
                uint32_t bh1 = *(uint32_t*)&Kh[key * BSTR + k0 + 2 * t + 8];
                uint32_t bl0 = *(uint32_t*)&Kl[key * BSTR + k0 + 2 * t];
                uint32_t bl1 = *(uint32_t*)&Kl[key * BSTR + k0 + 2 * t + 8];
                mma_bf16(sacc[fn], ah0, ah1, ah2, ah3, bh0, bh1);
                mma_bf16(sacc[fn], ah0, ah1, ah2, ah3, bl0, bl1);
                mma_bf16(sacc[fn], al0, al1, al2, al3, bh0, bh1);
            }
        }

        // ---- scale + mask ----
        const float scale = 0.125f;
        bool bnd = (s0 + 63 >= q0 + 2048);
#pragma unroll
        for (int fn = 0; fn < 8; fn++) {
#pragma unroll
            for (int e = 0; e < 4; e++) {
                float s = sacc[fn][e] * scale;
                if (bnd) {
                    int col = fn * 8 + 2 * t + (e & 1);
                    int rw  = (e < 2) ? row0 : row0 + 8;
                    if (s0 + col >= q0 + rw + 2048) s = -1e30f;
                }
                sacc[fn][e] = s;
            }
        }

        // ---- row max (warp-local over t: shfl xor 1,2) ----
        float rm0 = -INFINITY, rm1 = -INFINITY;
#pragma unroll
        for (int fn = 0; fn < 8; fn++) {
            rm0 = fmaxf(rm0, fmaxf(sacc[fn][0], sacc[fn][1]));
            rm1 = fmaxf(rm1, fmaxf(sacc[fn][2], sacc[fn][3]));
        }
        rm0 = fmaxf(rm0, __shfl_xor_sync(0xffffffffu, rm0, 1));
        rm0 = fmaxf(rm0, __shfl_xor_sync(0xffffffffu, rm0, 2));
        rm1 = fmaxf(rm1, __shfl_xor_sync(0xffffffffu, rm1, 1));
        rm1 = fmaxf(rm1, __shfl_xor_sync(0xffffffffu, rm1, 2));

        float mn0 = fmaxf(m0, rm0), mn1 = fmaxf(m1, rm1);
        float a0s = __expf(m0 - mn0), a1s = __expf(m1 - mn1);
        m0 = mn0; m1 = mn1;

        // ---- P = exp(S - m) in place, row sums ----
        float rs0 = 0.0f, rs1 = 0.0f;
#pragma unroll
        for (int fn = 0; fn < 8; fn++) {
            float p0 = __expf(sacc[fn][0] - m0);
            float p1 = __expf(sacc[fn][1] - m0);
            float p2 = __expf(sacc[fn][2] - m1);
            float p3 = __expf(sacc[fn][3] - m1);
            sacc[fn][0] = p0; sacc[fn][1] = p1;
            sacc[fn][2] = p2; sacc[fn][3] = p3;
            rs0 += p0 + p1; rs1 += p2 + p3;
        }
        rs0 += __shfl_xor_sync(0xffffffffu, rs0, 1);
        rs0 += __shfl_xor_sync(0xffffffffu, rs0, 2);
        rs1 += __shfl_xor_sync(0xffffffffu, rs1, 1);
        rs1 += __shfl_xor_sync(0xffffffffu, rs1, 2);
        l0 = l0 * a0s + rs0;
        l1 = l1 * a1s + rs1;

#pragma unroll
        for (int fn = 0; fn < 8; fn++) {
            O[fn][0] *= a0s; O[fn][1] *= a0s;
            O[fn][2] *= a1s; O[fn][3] *= a1s;
        }

        // ---- O += P V: A-fragment = accumulator layout (no shfl) ----
#pragma unroll
        for (int ks = 0; ks < 4; ks++) {
            int k0 = ks << 4;
            __nv_bfloat16 h00, r00, h01, r01, h02, r02, h03, r03;
            __nv_bfloat16 h10, r10, h11, r11, h12, r12, h13, r13;
            bsplit(sacc[2 * ks][0], h00, r00);     bsplit(sacc[2 * ks][1], h01, r01);
            bsplit(sacc[2 * ks][2], h02, r02);     bsplit(sacc[2 * ks][3], h03, r03);
            bsplit(sacc[2 * ks + 1][0], h10, r10); bsplit(sacc[2 * ks + 1][1], h11, r11);
            bsplit(sacc[2 * ks + 1][2], h12, r12); bsplit(sacc[2 * ks + 1][3], h13, r13);
            uint32_t ph0 = bpack(h00, h01), ph1 = bpack(h02, h03);
            uint32_t ph2 = bpack(h10, h11), ph3 = bpack(h12, h13);
            uint32_t pl0 = bpack(r00, r01), pl1 = bpack(r02, r03);
            uint32_t pl2 = bpack(r10, r11), pl3 = bpack(r12, r13);
#pragma unroll
            for (int fn = 0; fn < 8; fn++) {
                int dd = fn * 8 + g;
                uint32_t vh0 = *(uint32_t*)&Vh[dd * BSTR + k0 + 2 * t];
                uint32_t vh1 = *(uint32_t*)&Vh[dd * BSTR + k0 + 2 * t + 8];
                uint32_t vl0 = *(uint32_t*)&Vl[dd * BSTR + k0 + 2 * t];
                uint32_t vl1 = *(uint32_t*)&Vl[dd * BSTR + k0 + 2 * t + 8];
                mma_bf16(O[fn], ph0, ph1, ph2, ph3, vh0, vh1);
                mma_bf16(O[fn], ph0, ph1, ph2, ph3, vl0, vl1);
                mma_bf16(O[fn], pl0, pl1, pl2, pl3, vh0, vh1);
            }
        }

        __syncthreads();   // all warps done reading buffer p
        int nt = tt + 2;
        if (nt < te) {
            load_tile_async(tid, col0, nt << 6, Khi_g, Klo_g, VThi_g, VTlo_g,
                            Kh_s + p * 64 * BSTR, Kl_s + p * 64 * BSTR,
                            Vh_s + p * 64 * BSTR, Vl_s + p * 64 * BSTR);
        }
        CP_COMMIT();   // keep group numbering aligned even when empty
    }

    // ---- store unnormalized partial O + (m, l) ----
#pragma unroll
    for (int fn = 0; fn < 8; fn++) {
        int col = fn * 8 + 2 * t;
        *(float2*)&g_Op[split][h][qb][row0][col]     = make_float2(O[fn][0], O[fn][1]);
        *(float2*)&g_Op[split][h][qb][row0 + 8][col] = make_float2(O[fn][2], O[fn][3]);
    }
    if (t == 0) {
        g_ml[split][h][qb][0][row0] = m0;     g_ml[split][h][qb][1][row0] = l0;
        g_ml[split][h][qb][0][row0 + 8] = m1; g_ml[split][h][qb][1][row0 + 8] = l1;
    }
}

// ---------------------------------------------------------------------------
// Combine the two key-split halves: Y = (e0*O0 + e1*O1) / (e0*l0 + e1*l1)
// ---------------------------------------------------------------------------
__global__ __launch_bounds__(256) void attn_combine_kernel(float* __restrict__ Y)
{
    int qb = blockIdx.x, h = blockIdx.y;
    int tid = threadIdx.x;
    int row = tid >> 1;            // 0..127
    int c0 = (tid & 1) << 5;       // 0 or 32

    float m0 = g_ml[0][h][qb][0][row], l0 = g_ml[0][h][qb][1][row];
    float m1 = g_ml[1][h][qb][0][row], l1 = g_ml[1][h][qb][1][row];
    float M = fmaxf(m0, m1);
    float e0 = __expf(m0 - M), e1 = __expf(m1 - M);
    float inv = 1.0f / (e0 * l0 + e1 * l1);
    float s0 = e0 * inv, s1 = e1 * inv;

    const float* O0 = &g_Op[0][h][qb][row][c0];
    const float* O1 = &g_Op[1][h][qb][row][c0];
    float* y = &Y[(size_t)((qb << 7) + row) * D_MOD + h * HDIM + c0];
#pragma unroll
    for (int c = 0; c < 32; c += 4) {
        float4 a = *(const float4*)&O0[c];
        float4 b = *(const float4*)&O1[c];
        float4 r;
        r.x = a.x * s0 + b.x * s1;
        r.y = a.y * s0 + b.y * s1;
        r.z = a.z * s0 + b.z * s1;
        r.w = a.w * s0 + b.w * s1;
        *(float4*)&y[c] = r;
    }
}

// ---------------------------------------------------------------------------
extern "C" void kernel_launch(void* const* d_in, const int* in_sizes, int n_in,
                              void* d_out, int out_size)
{
    (void)in_sizes; (void)n_in; (void)out_size;
    const float* l        = (const float*)d_in[0];
    const float* x        = (const float*)d_in[1];
    const float* W_attn_l = (const float*)d_in[2];
    const float* b_attn_l = (const float*)d_in[3];
    const float* W_attn_c = (const float*)d_in[4];
    const float* b_attn_c = (const float*)d_in[5];
    const float* W_q      = (const float*)d_in[6];
    const float* b_q      = (const float*)d_in[7];
    const float* W_proj   = (const float*)d_in[8];
    const float* b_proj   = (const float*)d_in[9];
    float* out = (float*)d_out;

    __nv_bfloat16 *Khi, *Klo, *VThi, *VTlo, *Qhi, *Qlo;
    float* Yp;
    cudaGetSymbolAddress((void**)&Khi, g_Khi);
    cudaGetSymbolAddress((void**)&Klo, g_Klo);
    cudaGetSymbolAddress((void**)&VThi, g_VThi);
    cudaGetSymbolAddress((void**)&VTlo, g_VTlo);
    cudaGetSymbolAddress((void**)&Qhi, g_Qhi);
    cudaGetSymbolAddress((void**)&Qlo, g_Qlo);
    cudaGetSymbolAddress((void**)&Yp, g_Y);

    dim3 blk(256);

    // merged QKV projections: one launch, grid (40, 16)
    gemm_qkv_kernel<<<dim3(40, 16), blk>>>(l, x,
        W_attn_l, b_attn_l, W_attn_c, b_attn_c, W_q, b_q,
        Khi, Klo, VThi, VTlo, Qhi, Qlo);

    // attention: 32 (qb-desc, split) x 16 heads; smem = 110592 B (2 CTA/SM)
    size_t smem = (size_t)(2 * 128 + 8 * 64) * BSTR * sizeof(__nv_bfloat16);
    cudaFuncSetAttribute(attn_mma_kernel, cudaFuncAttributeMaxDynamicSharedMemorySize, (int)smem);
    attn_mma_kernel<<<dim3(32, 16), blk, smem>>>(Qhi, Qlo, Khi, Klo, VThi, VTlo);

    // combine split halves -> Y
    attn_combine_kernel<<<dim3(16, 16), blk>>>(Yp);

    // output projection
    gemm_proj_kernel<<<dim3(8, 16), blk>>>(Yp, W_proj, b_proj, out);
}

// round 14
// speedup vs baseline: 1.1842x; 1.1842x over previous
#include <cuda_runtime.h>
#include <cuda_bf16.h>
#include <math.h>
#include <stdint.h>

// Problem constants: B=1, T=2048, D=1024, H=16, HD=64
#define T_SEQ 2048
#define D_MOD 1024
#define NH    16
#define HDIM  64

// Scratch (allocation-free rule: __device__ globals)
__device__ __nv_bfloat16 g_Khi[4096 * 1024];   // K natural [s][1024]
__device__ __nv_bfloat16 g_Klo[4096 * 1024];
__device__ __nv_bfloat16 g_VThi[1024 * 4096];  // V transposed [d][4096]
__device__ __nv_bfloat16 g_VTlo[1024 * 4096];
__device__ __nv_bfloat16 g_Qhi[2048 * 1024];   // Q natural [q][1024]
__device__ __nv_bfloat16 g_Qlo[2048 * 1024];
__device__ float g_Y[T_SEQ * D_MOD];           // attention output (fp32, proj input)
// split-KV partials
__device__ float g_Op[2][NH][16][128][64];     // unnormalized partial O
__device__ float g_ml[2][NH][16][2][128];      // [0]=m, [1]=l per row

// ---------------------------------------------------------------------------
// helpers
// ---------------------------------------------------------------------------
__device__ __forceinline__ float to_tf32(float f) {
    uint32_t u;
    asm("cvt.rna.tf32.f32 %0, %1;" : "=r"(u) : "f"(f));
    return __uint_as_float(u);
}

__device__ __forceinline__ void mma_tf32(float* c,
    uint32_t a0, uint32_t a1, uint32_t a2, uint32_t a3,
    uint32_t b0, uint32_t b1)
{
    asm volatile(
        "mma.sync.aligned.m16n8k8.row.col.f32.tf32.tf32.f32 "
        "{%0,%1,%2,%3}, {%4,%5,%6,%7}, {%8,%9}, {%0,%1,%2,%3};\n"
        : "+f"(c[0]), "+f"(c[1]), "+f"(c[2]), "+f"(c[3])
        : "r"(a0), "r"(a1), "r"(a2), "r"(a3), "r"(b0), "r"(b1));
}

__device__ __forceinline__ void mma_bf16(float* c,
    uint32_t a0, uint32_t a1, uint32_t a2, uint32_t a3,
    uint32_t b0, uint32_t b1)
{
    asm volatile(
        "mma.sync.aligned.m16n8k16.row.col.f32.bf16.bf16.f32 "
        "{%0,%1,%2,%3}, {%4,%5,%6,%7}, {%8,%9}, {%0,%1,%2,%3};\n"
        : "+f"(c[0]), "+f"(c[1]), "+f"(c[2]), "+f"(c[3])
        : "r"(a0), "r"(a1), "r"(a2), "r"(a3), "r"(b0), "r"(b1));
}

__device__ __forceinline__ void bsplit(float x, __nv_bfloat16& h, __nv_bfloat16& l) {
    h = __float2bfloat16(x);
    l = __float2bfloat16(x - __bfloat162float(h));
}

__device__ __forceinline__ uint32_t bpack(__nv_bfloat16 lo, __nv_bfloat16 hi) {
    __nv_bfloat162 p = __halves2bfloat162(lo, hi);   // lo -> bits[0:16)
    return *(uint32_t*)&p;
}

__device__ __forceinline__ void cp16(uint32_t dst, const void* src) {
    asm volatile("cp.async.cg.shared.global [%0], [%1], 16;\n" :: "r"(dst), "l"(src));
}
#define CP_COMMIT() asm volatile("cp.async.commit_group;\n" ::: "memory")
#define CP_WAIT1()  asm volatile("cp.async.wait_group 1;\n" ::: "memory")

__device__ __forceinline__ uint32_t sma(const void* p) {
    return (uint32_t)__cvta_generic_to_shared(p);
}

// ---------------------------------------------------------------------------
// GEMM core — REVERTED to the measured-good R12 layout:
// As[128 rows][36] transposed-K interleave?  No: As is [128 m][AS_STRIDE k],
// Bs[32 k][BS_STRIDE n], identical loads/stores/mma order to R12.
// ---------------------------------------------------------------------------
#define AS_STRIDE 36
#define BS_STRIDE 136
#define GEMM_SMEM_FLOATS (128 * AS_STRIDE + 32 * BS_STRIDE)   // 8960 floats

__device__ __forceinline__ void gemm_core(
    const float* __restrict__ A, const float* __restrict__ W,
    int N, int m0, int n0, int tid,
    float* __restrict__ As, float* __restrict__ Bs, float acc[4][4][4])
{
    const int wid  = tid >> 5;
    const int lane = tid & 31;
    const int g    = lane >> 2;
    const int t    = lane & 3;
    const int warp_m = wid >> 2;
    const int warp_n = wid & 3;

    int ar[4], ac[4], br[4], bc[4];
#pragma unroll
    for (int i = 0; i < 4; i++) {
        int lin = tid + (i << 8);
        ar[i] = lin >> 3;
        ac[i] = (lin & 7) << 2;
        br[i] = lin >> 5;
        bc[i] = (lin & 31) << 2;
    }

    float4 pa[4], pb[4];
#pragma unroll
    for (int i = 0; i < 4; i++) {
        pa[i] = *(const float4*)&A[(size_t)(m0 + ar[i]) * 1024 + ac[i]];
        pb[i] = *(const float4*)&W[(size_t)br[i] * N + n0 + bc[i]];
    }

    for (int kt = 0; kt < 32; kt++) {
#pragma unroll
        for (int i = 0; i < 4; i++) {
            float* pdst = &As[ar[i] * AS_STRIDE + ac[i]];
            pdst[0] = to_tf32(pa[i].x); pdst[1] = to_tf32(pa[i].y);
            pdst[2] = to_tf32(pa[i].z); pdst[3] = to_tf32(pa[i].w);
            float* qdst = &Bs[br[i] * BS_STRIDE + bc[i]];
            qdst[0] = to_tf32(pb[i].x); qdst[1] = to_tf32(pb[i].y);
            qdst[2] = to_tf32(pb[i].z); qdst[3] = to_tf32(pb[i].w);
        }
        __syncthreads();

        if (kt < 31) {
            int k0 = (kt + 1) << 5;
#pragma unroll
            for (int i = 0; i < 4; i++) {
                pa[i] = *(const float4*)&A[(size_t)(m0 + ar[i]) * 1024 + k0 + ac[i]];
                pb[i] = *(const float4*)&W[(size_t)(k0 + br[i]) * N + n0 + bc[i]];
            }
        }

#pragma unroll
        for (int ks = 0; ks < 4; ks++) {
            int k0 = ks << 3;
            uint32_t b0[4], b1[4];
#pragma unroll
            for (int fn = 0; fn < 4; fn++) {
                int nb = warp_n * 32 + fn * 8 + g;
                b0[fn] = __float_as_uint(Bs[(k0 + t) * BS_STRIDE + nb]);
                b1[fn] = __float_as_uint(Bs[(k0 + t + 4) * BS_STRIDE + nb]);
            }
#pragma unroll
            for (int fm = 0; fm < 4; fm++) {
                int mr = warp_m * 64 + fm * 16 + g;
                uint32_t a0 = __float_as_uint(As[mr * AS_STRIDE + k0 + t]);
                uint32_t a1 = __float_as_uint(As[(mr + 8) * AS_STRIDE + k0 + t]);
                uint32_t a2 = __float_as_uint(As[mr * AS_STRIDE + k0 + 4 + t]);
                uint32_t a3 = __float_as_uint(As[(mr + 8) * AS_STRIDE + k0 + 4 + t]);
#pragma unroll
                for (int fn = 0; fn < 4; fn++)
                    mma_tf32(acc[fm][fn], a0, a1, a2, a3, b0[fn], b1[fn]);
            }
        }
        __syncthreads();
    }
}

// ---------------------------------------------------------------------------
// Merged QKV projection GEMM: grid (40, 16).
//   bx in [0,16):  l  @ W_attn_l -> K rows 0:2048 / VT (rowoff 0)
//   bx in [16,32): x  @ W_attn_c -> K rows 2048:4096 / VT (rowoff 2048)
//   bx in [32,40): x  @ W_q      -> Q (natural bf16 hi/lo)
// ---------------------------------------------------------------------------
__global__ __launch_bounds__(256) void gemm_qkv_kernel(
    const float* __restrict__ lin_, const float* __restrict__ xin_,
    const float* __restrict__ Wl, const float* __restrict__ bl,
    const float* __restrict__ Wc, const float* __restrict__ bc2,
    const float* __restrict__ Wq, const float* __restrict__ bq,
    __nv_bfloat16* __restrict__ Khi, __nv_bfloat16* __restrict__ Klo,
    __nv_bfloat16* __restrict__ VThi, __nv_bfloat16* __restrict__ VTlo,
    __nv_bfloat16* __restrict__ Qhi, __nv_bfloat16* __restrict__ Qlo)
{
    __shared__ float smem[GEMM_SMEM_FLOATS];
    float* As = smem;
    float* Bs = smem + 128 * AS_STRIDE;

    const int bx = blockIdx.x;
    const float *A, *W, *bias;
    int N, rowoff, n0;
    bool qmode;
    if (bx < 16)      { A = lin_; W = Wl; bias = bl;  N = 2048; rowoff = 0;    n0 = bx << 7;        qmode = false; }
    else if (bx < 32) { A = xin_; W = Wc; bias = bc2; N = 2048; rowoff = 2048; n0 = (bx - 16) << 7; qmode = false; }
    else              { A = xin_; W = Wq; bias = bq;  N = 1024; rowoff = 0;    n0 = (bx - 32) << 7; qmode = true;  }
    const int m0 = blockIdx.y << 7;

    float acc[4][4][4];
#pragma unroll
    for (int fm = 0; fm < 4; fm++)
#pragma unroll
        for (int fn = 0; fn < 4; fn++)
#pragma unroll
            for (int e = 0; e < 4; e++) acc[fm][fn][e] = 0.0f;

    gemm_core(A, W, N, m0, n0, threadIdx.x, As, Bs, acc);

    const int tid  = threadIdx.x;
    const int wid  = tid >> 5;
    const int lane = tid & 31;
    const int g    = lane >> 2;
    const int t    = lane & 3;
    const int warp_m = wid >> 2;
    const int warp_n = wid & 3;

#pragma unroll
    for (int fm = 0; fm < 4; fm++) {
        int row = m0 + warp_m * 64 + fm * 16 + g;
        int srow = rowoff + row;
#pragma unroll
        for (int fn = 0; fn < 4; fn++) {
            int col = n0 + warp_n * 32 + fn * 8 + 2 * t;
            float bx0 = bias[col], by0 = bias[col + 1];
            float v0x = acc[fm][fn][0] + bx0, v0y = acc[fm][fn][1] + by0;
            float v1x = acc[fm][fn][2] + bx0, v1y = acc[fm][fn][3] + by0;
            __nv_bfloat16 h0, l0, h1, l1, h2, l2, h3, l3;
            bsplit(v0x, h0, l0); bsplit(v0y, h1, l1);
            bsplit(v1x, h2, l2); bsplit(v1y, h3, l3);
            if (qmode) {
                *(uint32_t*)&Qhi[(size_t)srow * 1024 + col] = bpack(h0, h1);
                *(uint32_t*)&Qlo[(size_t)srow * 1024 + col] = bpack(l0, l1);
                *(uint32_t*)&Qhi[(size_t)(srow + 8) * 1024 + col] = bpack(h2, h3);
                *(uint32_t*)&Qlo[(size_t)(srow + 8) * 1024 + col] = bpack(l2, l3);
            } else if (col < 1024) {
                *(uint32_t*)&Khi[(size_t)srow * 1024 + col] = bpack(h0, h1);
                *(uint32_t*)&Klo[(size_t)srow * 1024 + col] = bpack(l0, l1);
                *(uint32_t*)&Khi[(size_t)(srow + 8) * 1024 + col] = bpack(h2, h3);
                *(uint32_t*)&Klo[(size_t)(srow + 8) * 1024 + col] = bpack(l2, l3);
            } else {
                int d0 = col - 1024;
                VThi[(size_t)d0 * 4096 + srow] = h0;        VTlo[(size_t)d0 * 4096 + srow] = l0;
                VThi[(size_t)(d0 + 1) * 4096 + srow] = h1;  VTlo[(size_t)(d0 + 1) * 4096 + srow] = l1;
                VThi[(size_t)d0 * 4096 + srow + 8] = h2;    VTlo[(size_t)d0 * 4096 + srow + 8] = l2;
                VThi[(size_t)(d0 + 1) * 4096 + srow + 8] = h3; VTlo[(size_t)(d0 + 1) * 4096 + srow + 8] = l3;
            }
        }
    }
}

// Output projection GEMM (fp32 epilogue), same core.
__global__ __launch_bounds__(256) void gemm_proj_kernel(
    const float* __restrict__ A, const float* __restrict__ W,
    const float* __restrict__ bias, float* __restrict__ outf)
{
    __shared__ float smem[GEMM_SMEM_FLOATS];
    float* As = smem;
    float* Bs = smem + 128 * AS_STRIDE;

    const int n0 = blockIdx.x << 7;
    const int m0 = blockIdx.y << 7;

    float acc[4][4][4];
#pragma unroll
    for (int fm = 0; fm < 4; fm++)
#pragma unroll
        for (int fn = 0; fn < 4; fn++)
#pragma unroll
            for (int e = 0; e < 4; e++) acc[fm][fn][e] = 0.0f;

    gemm_core(A, W, 1024, m0, n0, threadIdx.x, As, Bs, acc);

    const int tid  = threadIdx.x;
    const int wid  = tid >> 5;
    const int lane = tid & 31;
    const int g    = lane >> 2;
    const int t    = lane & 3;
    const int warp_m = wid >> 2;
    const int warp_n = wid & 3;

#pragma unroll
    for (int fm = 0; fm < 4; fm++) {
        int row = m0 + warp_m * 64 + fm * 16 + g;
#pragma unroll
        for (int fn = 0; fn < 4; fn++) {
            int col = n0 + warp_n * 32 + fn * 8 + 2 * t;
            float bx0 = bias[col], by0 = bias[col + 1];
            *(float2*)&outf[(size_t)row * 1024 + col] =
                make_float2(acc[fm][fn][0] + bx0, acc[fm][fn][1] + by0);
            *(float2*)&outf[(size_t)(row + 8) * 1024 + col] =
                make_float2(acc[fm][fn][2] + bx0, acc[fm][fn][3] + by0);
        }
    }
}

// ---------------------------------------------------------------------------
// Tensor-core flash attention v5 (unchanged, measured-good R12): split-KV.
// ---------------------------------------------------------------------------
#define BSTR 72   // bf16 row stride (144 B = 36 words; bank = 4*row + t)

__device__ __forceinline__ void load_tile_async(
    int tid, int col0, int s0,
    const __nv_bfloat16* __restrict__ Khi_g, const __nv_bfloat16* __restrict__ Klo_g,
    const __nv_bfloat16* __restrict__ VThi_g, const __nv_bfloat16* __restrict__ VTlo_g,
    __nv_bfloat16* Kh, __nv_bfloat16* Kl, __nv_bfloat16* Vh, __nv_bfloat16* Vl)
{
#pragma unroll
    for (int c = 0; c < 2; c++) {
        int idx = (tid << 1) + c;          // 0..511
        int j = idx >> 3;                  // 0..63
        int ch = (idx & 7) << 3;           // bf16 offset, 16B chunks
        cp16(sma(Kh + j * BSTR + ch), Khi_g + (size_t)(s0 + j) * 1024 + col0 + ch);
        cp16(sma(Kl + j * BSTR + ch), Klo_g + (size_t)(s0 + j) * 1024 + col0 + ch);
        cp16(sma(Vh + j * BSTR + ch), VThi_g + (size_t)(col0 + j) * 4096 + s0 + ch);
        cp16(sma(Vl + j * BSTR + ch), VTlo_g + (size_t)(col0 + j) * 4096 + s0 + ch);
    }
}

__global__ __launch_bounds__(256, 2) void attn_mma_kernel(
    const __nv_bfloat16* __restrict__ Qhi_g, const __nv_bfloat16* __restrict__ Qlo_g,
    const __nv_bfloat16* __restrict__ Khi_g, const __nv_bfloat16* __restrict__ Klo_g,
    const __nv_bfloat16* __restrict__ VThi_g, const __nv_bfloat16* __restrict__ VTlo_g)
{
    extern __shared__ char smraw[];
    __nv_bfloat16* Qhi_s = (__nv_bfloat16*)smraw;     // [128][BSTR]
    __nv_bfloat16* Qlo_s = Qhi_s + 128 * BSTR;
    __nv_bfloat16* Kh_s  = Qlo_s + 128 * BSTR;        // [2][64][BSTR]
    __nv_bfloat16* Kl_s  = Kh_s + 2 * 64 * BSTR;
    __nv_bfloat16* Vh_s  = Kl_s + 2 * 64 * BSTR;
    __nv_bfloat16* Vl_s  = Vh_s + 2 * 64 * BSTR;

    const int tid  = threadIdx.x;
    const int wid  = tid >> 5;
    const int lane = tid & 31;
    const int g    = lane >> 2;   // 0..7
    const int t    = lane & 3;    // 0..3

    const int bx = blockIdx.x;               // 0..31, largest work first
    const int qb = 15 - (bx >> 1);
    const int split = bx & 1;
    const int h  = blockIdx.y;
    const int q0 = qb << 7;
    const int col0 = h * HDIM;

    const int nt_total = 2 * qb + 34;        // 34..64
    const int nt0 = nt_total >> 1;           // 17..32
    const int tb = split ? nt0 : 0;
    const int te = split ? nt_total : nt0;

    const int row0 = wid * 16 + g;

    // ---- prologue: async-load Q + tiles tb, tb+1 ----
#pragma unroll
    for (int c = 0; c < 4; c++) {
        int idx = (tid << 2) + c;          // 0..1023
        int r = idx >> 3;
        int ch = (idx & 7) << 3;
        cp16(sma(Qhi_s + r * BSTR + ch), Qhi_g + (size_t)(q0 + r) * 1024 + col0 + ch);
        cp16(sma(Qlo_s + r * BSTR + ch), Qlo_g + (size_t)(q0 + r) * 1024 + col0 + ch);
    }
    load_tile_async(tid, col0, tb << 6, Khi_g, Klo_g, VThi_g, VTlo_g,
                    Kh_s, Kl_s, Vh_s, Vl_s);
    CP_COMMIT();
    load_tile_async(tid, col0, (tb + 1) << 6, Khi_g, Klo_g, VThi_g, VTlo_g,
                    Kh_s + 64 * BSTR, Kl_s + 64 * BSTR, Vh_s + 64 * BSTR, Vl_s + 64 * BSTR);
    CP_COMMIT();

    float O[8][4];
#pragma unroll
    for (int fn = 0; fn < 8; fn++)
#pragma unroll
        for (int e = 0; e < 4; e++) O[fn][e] = 0.0f;
    float m0 = -INFINITY, m1 = -INFINITY, l0 = 0.0f, l1 = 0.0f;

    for (int tt = tb; tt < te; tt++) {
        int s0 = tt << 6;
        int p = (tt - tb) & 1;
        const __nv_bfloat16* Kh = Kh_s + p * 64 * BSTR;
        const __nv_bfloat16* Kl = Kl_s + p * 64 * BSTR;
        const __nv_bfloat16* Vh = Vh_s + p * 64 * BSTR;
        const __nv_bfloat16* Vl = Vl_s + p * 64 * BSTR;

        CP_WAIT1();
        __syncthreads();

        // ---- S = Q K^T via 3-mma bf16 split (lo*lo dropped) ----
        float sacc[8][4];
#pragma unroll
        for (int fn = 0; fn < 8; fn++)
#pragma unroll
            for (int e = 0; e < 4; e++) sacc[fn][e] = 0.0f;

#pragma unroll
        for (int ks = 0; ks < 4; ks++) {
            int k0 = ks << 4;
            uint32_t ah0 = *(uint32_t*)&Qhi_s[row0 * BSTR + k0 + 2 * t];
            uint32_t ah1 = *(uint32_t*)&Qhi_s[(row0 + 8) * BSTR + k0 + 2 * t];
            uint32_t ah2 = *(uint32_t*)&Qhi_s[row0 * BSTR + k0 + 2 * t + 8];
            uint32_t ah3 = *(uint32_t*)&Qhi_s[(row0 + 8) * BSTR + k0 + 2 * t + 8];
            uint32_t al0 = *(uint32_t*)&Qlo_s[row0 * BSTR + k0 + 2 * t];
            uint32_t al1 = *(uint32_t*)&Qlo_s[(row0 + 8) * BSTR + k0 + 2 * t];
            uint32_t al2 = *(uint32_t*)&Qlo_s[row0 * BSTR + k0 + 2 * t + 8];
            uint32_t al3 = *(uint32_t*)&Qlo_s[(row0 + 8) * BSTR + k0 + 2 * t + 8];
#pragma unroll
            for (int fn = 0; fn < 8; fn++) {
                int key = fn * 8 + g;
                uint32_t bh0 = *(uint32_t*)&Kh[key * BSTR + k0 + 2 * t];
                uint32_t bh1 = *(uint32_t*)&Kh[key * BSTR + k0 + 2 * t + 8];
                uint32_t bl0 = *(uint32_t*)&Kl[key * BSTR + k0 + 2 * t];
                uint32_t bl1 = *(uint32_t*)&Kl[key * BSTR + k0 + 2 * t + 8];
                mma_bf16(sacc[fn], ah0, ah1, ah2, ah3, bh0, bh1);
                mma_bf16(sacc[fn], ah0, ah1, ah2, ah3, bl0, bl1);
                mma_bf16(sacc[fn], al0, al1, al2, al3, bh0, bh1);
            }
        }

        // ---- scale + mask ----
        const float scale = 0.125f;
        bool bnd = (s0 + 63 >= q0 + 2048);
#pragma unroll
        for (int fn = 0; fn < 8; fn++) {
#pragma unroll
            for (int e = 0; e < 4; e++) {
                float s = sacc[fn][e] * scale;
                if (bnd) {
                    int col = fn * 8 + 2 * t + (e & 1);
                    int rw  = (e < 2) ? row0 : row0 + 8;
                    if (s0 + col >= q0 + rw + 2048) s = -1e30f;
                }
                sacc[fn][e] = s;
            }
        }

        // ---- row max (warp-local over t: shfl xor 1,2) ----
        float rm0 = -INFINITY, rm1 = -INFINITY;
#pragma unroll
        for (int fn = 0; fn < 8; fn++) {
            rm0 = fmaxf(rm0, fmaxf(sacc[fn][0], sacc[fn][1]));
            rm1 = fmaxf(rm1, fmaxf(sacc[fn][2], sacc[fn][3]));
        }
        rm0 = fmaxf(rm0, __shfl_xor_sync(0xffffffffu, rm0, 1));
        rm0 = fmaxf(rm0, __shfl_xor_sync(0xffffffffu, rm0, 2));
        rm1 = fmaxf(rm1, __shfl_xor_sync(0xffffffffu, rm1, 1));
        rm1 = fmaxf(rm1, __shfl_xor_sync(0xffffffffu, rm1, 2));

        float mn0 = fmaxf(m0, rm0), mn1 = fmaxf(m1, rm1);
        float a0s = __expf(m0 - mn0), a1s = __expf(m1 - mn1);
        m0 = mn0; m1 = mn1;

        // ---- P = exp(S - m) in place, row sums ----
        float rs0 = 0.0f, rs1 = 0.0f;
#pragma unroll
        for (int fn = 0; fn < 8; fn++) {
            float p0 = __expf(sacc[fn][0] - m0);
            float p1 = __expf(sacc[fn][1] - m0);
            float p2 = __expf(sacc[fn][2] - m1);
            float p3 = __expf(sacc[fn][3] - m1);
            sacc[fn][0] = p0; sacc[fn][1] = p1;
            sacc[fn][2] = p2; sacc[fn][3] = p3;
            rs0 += p0 + p1; rs1 += p2 + p3;
        }
        rs0 += __shfl_xor_sync(0xffffffffu, rs0, 1);
        rs0 += __shfl_xor_sync(0xffffffffu, rs0, 2);
        rs1 += __shfl_xor_sync(0xffffffffu, rs1, 1);
        rs1 += __shfl_xor_sync(0xffffffffu, rs1, 2);
        l0 = l0 * a0s + rs0;
        l1 = l1 * a1s + rs1;

#pragma unroll
        for (int fn = 0; fn < 8; fn++) {
            O[fn][0] *= a0s; O[fn][1] *= a0s;
            O[fn][2] *= a1s; O[fn][3] *= a1s;
        }

        // ---- O += P V: A-fragment = accumulator layout (no shfl) ----
#pragma unroll
        for (int ks = 0; ks < 4; ks++) {
            int k0 = ks << 4;
            __nv_bfloat16 h00, r00, h01, r01, h02, r02, h03, r03;
            __nv_bfloat16 h10, r10, h11, r11, h12, r12, h13, r13;
            bsplit(sacc[2 * ks][0], h00, r00);     bsplit(sacc[2 * ks][1], h01, r01);
            bsplit(sacc[2 * ks][2], h02, r02);     bsplit(sacc[2 * ks][3], h03, r03);
            bsplit(sacc[2 * ks + 1][0], h10, r10); bsplit(sacc[2 * ks + 1][1], h11, r11);
            bsplit(sacc[2 * ks + 1][2], h12, r12); bsplit(sacc[2 * ks + 1][3], h13, r13);
            uint32_t ph0 = bpack(h00, h01), ph1 = bpack(h02, h03);
            uint32_t ph2 = bpack(h10, h11), ph3 = bpack(h12, h13);
            uint32_t pl0 = bpack(r00, r01), pl1 = bpack(r02, r03);
            uint32_t pl2 = bpack(r10, r11), pl3 = bpack(r12, r13);
#pragma unroll
            for (int fn = 0; fn < 8; fn++) {
                int dd = fn * 8 + g;
                uint32_t vh0 = *(uint32_t*)&Vh[dd * BSTR + k0 + 2 * t];
                uint32_t vh1 = *(uint32_t*)&Vh[dd * BSTR + k0 + 2 * t + 8];
                uint32_t vl0 = *(uint32_t*)&Vl[dd * BSTR + k0 + 2 * t];
                uint32_t vl1 = *(uint32_t*)&Vl[dd * BSTR + k0 + 2 * t + 8];
                mma_bf16(O[fn], ph0, ph1, ph2, ph3, vh0, vh1);
                mma_bf16(O[fn], ph0, ph1, ph2, ph3, vl0, vl1);
                mma_bf16(O[fn], pl0, pl1, pl2, pl3, vh0, vh1);
            }
        }

        __syncthreads();   // all warps done reading buffer p
        int nt = tt + 2;
        if (nt < te) {
            load_tile_async(tid, col0, nt << 6, Khi_g, Klo_g, VThi_g, VTlo_g,
                            Kh_s + p * 64 * BSTR, Kl_s + p * 64 * BSTR,
                            Vh_s + p * 64 * BSTR, Vl_s + p * 64 * BSTR);
        }
        CP_COMMIT();   // keep group numbering aligned even when empty
    }

    // ---- store unnormalized partial O + (m, l) ----
#pragma unroll
    for (int fn = 0; fn < 8; fn++) {
        int col = fn * 8 + 2 * t;
        *(float2*)&g_Op[split][h][qb][row0][col]     = make_float2(O[fn][0], O[fn][1]);
        *(float2*)&g_Op[split][h][qb][row0 + 8][col] = make_float2(O[fn][2], O[fn][3]);
    }
    if (t == 0) {
        g_ml[split][h][qb][0][row0] = m0;     g_ml[split][h][qb][1][row0] = l0;
        g_ml[split][h][qb][0][row0 + 8] = m1; g_ml[split][h][qb][1][row0 + 8] = l1;
    }
}

// ---------------------------------------------------------------------------
// Combine the two key-split halves: Y = (e0*O0 + e1*O1) / (e0*l0 + e1*l1)
// ---------------------------------------------------------------------------
__global__ __launch_bounds__(256) void attn_combine_kernel(float* __restrict__ Y)
{
    int qb = blockIdx.x, h = blockIdx.y;
    int tid = threadIdx.x;
    int row = tid >> 1;            // 0..127
    int c0 = (tid & 1) << 5;       // 0 or 32

    float m0 = g_ml[0][h][qb][0][row], l0 = g_ml[0][h][qb][1][row];
    float m1 = g_ml[1][h][qb][0][row], l1 = g_ml[1][h][qb][1][row];
    float M = fmaxf(m0, m1);
    float e0 = __expf(m0 - M), e1 = __expf(m1 - M);
    float inv = 1.0f / (e0 * l0 + e1 * l1);
    float s0 = e0 * inv, s1 = e1 * inv;

    const float* O0 = &g_Op[0][h][qb][row][c0];
    const float* O1 = &g_Op[1][h][qb][row][c0];
    float* y = &Y[(size_t)((qb << 7) + row) * D_MOD + h * HDIM + c0];
#pragma unroll
    for (int c = 0; c < 32; c += 4) {
        float4 a = *(const float4*)&O0[c];
        float4 b = *(const float4*)&O1[c];
        float4 r;
        r.x = a.x * s0 + b.x * s1;
        r.y = a.y * s0 + b.y * s1;
        r.z = a.z * s0 + b.z * s1;
        r.w = a.w * s0 + b.w * s1;
        *(float4*)&y[c] = r;
    }
}

// ---------------------------------------------------------------------------
extern "C" void kernel_launch(void* const* d_in, const int* in_sizes, int n_in,
                              void* d_out, int out_size)
{
    (void)in_sizes; (void)n_in; (void)out_size;
    const float* l        = (const float*)d_in[0];
    const float* x        = (const float*)d_in[1];
    const float* W_attn_l = (const float*)d_in[2];
    const float* b_attn_l = (const float*)d_in[3];
    const float* W_attn_c = (const float*)d_in[4];
    const float* b_attn_c = (const float*)d_in[5];
    const float* W_q      = (const float*)d_in[6];
    const float* b_q      = (const float*)d_in[7];
    const float* W_proj   = (const float*)d_in[8];
    const float* b_proj   = (const float*)d_in[9];
    float* out = (float*)d_out;

    __nv_bfloat16 *Khi, *Klo, *VThi, *VTlo, *Qhi, *Qlo;
    float* Yp;
    cudaGetSymbolAddress((void**)&Khi, g_Khi);
    cudaGetSymbolAddress((void**)&Klo, g_Klo);
    cudaGetSymbolAddress((void**)&VThi, g_VThi);
    cudaGetSymbolAddress((void**)&VTlo, g_VTlo);
    cudaGetSymbolAddress((void**)&Qhi, g_Qhi);
    cudaGetSymbolAddress((void**)&Qlo, g_Qlo);
    cudaGetSymbolAddress((void**)&Yp, g_Y);

    dim3 blk(256);

    // merged QKV projections: one launch, grid (40, 16), R12 GEMM core
    gemm_qkv_kernel<<<dim3(40, 16), blk>>>(l, x,
        W_attn_l, b_attn_l, W_attn_c, b_attn_c, W_q, b_q,
        Khi, Klo, VThi, VTlo, Qhi, Qlo);

    // attention: 32 (qb-desc, split) x 16 heads; smem = 110592 B (2 CTA/SM)
    size_t smem = (size_t)(2 * 128 + 8 * 64) * BSTR * sizeof(__nv_bfloat16);
    cudaFuncSetAttribute(attn_mma_kernel, cudaFuncAttributeMaxDynamicSharedMemorySize, (int)smem);
    attn_mma_kernel<<<dim3(32, 16), blk, smem>>>(Qhi, Qlo, Khi, Klo, VThi, VTlo);

    // combine split halves -> Y
    attn_combine_kernel<<<dim3(16, 16), blk>>>(Yp);

    // output projection
    gemm_proj_kernel<<<dim3(8, 16), blk>>>(Yp, W_proj, b_proj, out);
}

// round 16
// speedup vs baseline: 1.4967x; 1.2640x over previous
#include <cuda_runtime.h>
#include <cuda_fp16.h>
#include <math.h>
#include <stdint.h>

// Problem constants: B=1, T=2048, D=1024, H=16, HD=64
#define T_SEQ 2048
#define D_MOD 1024
#define NH    16
#define HDIM  64

// Scratch (allocation-free rule: __device__ globals)
__device__ __half g_Kh[4096 * 1024];    // K natural [s][1024], fp16
__device__ __half g_Qh[2048 * 1024];    // Q natural [q][1024], fp16
__device__ __half g_VThi[1024 * 4096];  // V transposed [d][4096], fp16 hi
__device__ __half g_VTlo[1024 * 4096];  // fp16 lo (v - hi)
__device__ float g_Y[T_SEQ * D_MOD];    // attention output (fp32, proj input)
// split-KV partials
__device__ float g_Op[2][NH][16][128][64];
__device__ float g_ml[2][NH][16][2][128];

// ---------------------------------------------------------------------------
// helpers
// ---------------------------------------------------------------------------
__device__ __forceinline__ float to_tf32(float f) {
    uint32_t u;
    asm("cvt.rna.tf32.f32 %0, %1;" : "=r"(u) : "f"(f));
    return __uint_as_float(u);
}

__device__ __forceinline__ void mma_tf32(float* c,
    uint32_t a0, uint32_t a1, uint32_t a2, uint32_t a3,
    uint32_t b0, uint32_t b1)
{
    asm volatile(
        "mma.sync.aligned.m16n8k8.row.col.f32.tf32.tf32.f32 "
        "{%0,%1,%2,%3}, {%4,%5,%6,%7}, {%8,%9}, {%0,%1,%2,%3};\n"
        : "+f"(c[0]), "+f"(c[1]), "+f"(c[2]), "+f"(c[3])
        : "r"(a0), "r"(a1), "r"(a2), "r"(a3), "r"(b0), "r"(b1));
}

__device__ __forceinline__ void mma_f16(float* c,
    uint32_t a0, uint32_t a1, uint32_t a2, uint32_t a3,
    uint32_t b0, uint32_t b1)
{
    asm volatile(
        "mma.sync.aligned.m16n8k16.row.col.f32.f16.f16.f32 "
        "{%0,%1,%2,%3}, {%4,%5,%6,%7}, {%8,%9}, {%0,%1,%2,%3};\n"
        : "+f"(c[0]), "+f"(c[1]), "+f"(c[2]), "+f"(c[3])
        : "r"(a0), "r"(a1), "r"(a2), "r"(a3), "r"(b0), "r"(b1));
}

__device__ __forceinline__ void hsplit(float x, __half& h, __half& l) {
    h = __float2half(x);
    l = __float2half(x - __half2float(h));
}

__device__ __forceinline__ uint32_t hpack(__half lo, __half hi) {
    __half2 p = __halves2half2(lo, hi);   // lo -> bits[0:16)
    return *(uint32_t*)&p;
}

__device__ __forceinline__ void cp16(uint32_t dst, const void* src) {
    asm volatile("cp.async.cg.shared.global [%0], [%1], 16;\n" :: "r"(dst), "l"(src));
}
#define CP_COMMIT() asm volatile("cp.async.commit_group;\n" ::: "memory")
#define CP_WAIT1()  asm volatile("cp.async.wait_group 1;\n" ::: "memory")

__device__ __forceinline__ uint32_t sma(const void* p) {
    return (uint32_t)__cvta_generic_to_shared(p);
}

// ---------------------------------------------------------------------------
// GEMM core (measured-good R12/R14 layout, unchanged)
// ---------------------------------------------------------------------------
#define AS_STRIDE 36
#define BS_STRIDE 136
#define GEMM_SMEM_FLOATS (128 * AS_STRIDE + 32 * BS_STRIDE)

__device__ __forceinline__ void gemm_core(
    const float* __restrict__ A, const float* __restrict__ W,
    int N, int m0, int n0, int tid,
    float* __restrict__ As, float* __restrict__ Bs, float acc[4][4][4])
{
    const int wid  = tid >> 5;
    const int lane = tid & 31;
    const int g    = lane >> 2;
    const int t    = lane & 3;
    const int warp_m = wid >> 2;
    const int warp_n = wid & 3;

    int ar[4], ac[4], br[4], bc[4];
#pragma unroll
    for (int i = 0; i < 4; i++) {
        int lin = tid + (i << 8);
        ar[i] = lin >> 3;
        ac[i] = (lin & 7) << 2;
        br[i] = lin >> 5;
        bc[i] = (lin & 31) << 2;
    }

    float4 pa[4], pb[4];
#pragma unroll
    for (int i = 0; i < 4; i++) {
        pa[i] = *(const float4*)&A[(size_t)(m0 + ar[i]) * 1024 + ac[i]];
        pb[i] = *(const float4*)&W[(size_t)br[i] * N + n0 + bc[i]];
    }

    for (int kt = 0; kt < 32; kt++) {
#pragma unroll
        for (int i = 0; i < 4; i++) {
            float* pdst = &As[ar[i] * AS_STRIDE + ac[i]];
            pdst[0] = to_tf32(pa[i].x); pdst[1] = to_tf32(pa[i].y);
            pdst[2] = to_tf32(pa[i].z); pdst[3] = to_tf32(pa[i].w);
            float* qdst = &Bs[br[i] * BS_STRIDE + bc[i]];
            qdst[0] = to_tf32(pb[i].x); qdst[1] = to_tf32(pb[i].y);
            qdst[2] = to_tf32(pb[i].z); qdst[3] = to_tf32(pb[i].w);
        }
        __syncthreads();

        if (kt < 31) {
            int k0 = (kt + 1) << 5;
#pragma unroll
            for (int i = 0; i < 4; i++) {
                pa[i] = *(const float4*)&A[(size_t)(m0 + ar[i]) * 1024 + k0 + ac[i]];
                pb[i] = *(const float4*)&W[(size_t)(k0 + br[i]) * N + n0 + bc[i]];
            }
        }

#pragma unroll
        for (int ks = 0; ks < 4; ks++) {
            int k0 = ks << 3;
            uint32_t b0[4], b1[4];
#pragma unroll
            for (int fn = 0; fn < 4; fn++) {
                int nb = warp_n * 32 + fn * 8 + g;
                b0[fn] = __float_as_uint(Bs[(k0 + t) * BS_STRIDE + nb]);
                b1[fn] = __float_as_uint(Bs[(k0 + t + 4) * BS_STRIDE + nb]);
            }
#pragma unroll
            for (int fm = 0; fm < 4; fm++) {
                int mr = warp_m * 64 + fm * 16 + g;
                uint32_t a0 = __float_as_uint(As[mr * AS_STRIDE + k0 + t]);
                uint32_t a1 = __float_as_uint(As[(mr + 8) * AS_STRIDE + k0 + t]);
                uint32_t a2 = __float_as_uint(As[mr * AS_STRIDE + k0 + 4 + t]);
                uint32_t a3 = __float_as_uint(As[(mr + 8) * AS_STRIDE + k0 + 4 + t]);
#pragma unroll
                for (int fn = 0; fn < 4; fn++)
                    mma_tf32(acc[fm][fn], a0, a1, a2, a3, b0[fn], b1[fn]);
            }
        }
        __syncthreads();
    }
}

// ---------------------------------------------------------------------------
// Merged QKV projection GEMM: grid (40, 16). fp16 epilogues.
// ---------------------------------------------------------------------------
__global__ __launch_bounds__(256) void gemm_qkv_kernel(
    const float* __restrict__ lin_, const float* __restrict__ xin_,
    const float* __restrict__ Wl, const float* __restrict__ bl,
    const float* __restrict__ Wc, const float* __restrict__ bc2,
    const float* __restrict__ Wq, const float* __restrict__ bq,
    __half* __restrict__ Kh, __half* __restrict__ Qh,
    __half* __restrict__ VThi, __half* __restrict__ VTlo)
{
    __shared__ float smem[GEMM_SMEM_FLOATS];
    float* As = smem;
    float* Bs = smem + 128 * AS_STRIDE;

    const int bx = blockIdx.x;
    const float *A, *W, *bias;
    int N, rowoff, n0;
    bool qmode;
    if (bx < 16)      { A = lin_; W = Wl; bias = bl;  N = 2048; rowoff = 0;    n0 = bx << 7;        qmode = false; }
    else if (bx < 32) { A = xin_; W = Wc; bias = bc2; N = 2048; rowoff = 2048; n0 = (bx - 16) << 7; qmode = false; }
    else              { A = xin_; W = Wq; bias = bq;  N = 1024; rowoff = 0;    n0 = (bx - 32) << 7; qmode = true;  }
    const int m0 = blockIdx.y << 7;

    float acc[4][4][4];
#pragma unroll
    for (int fm = 0; fm < 4; fm++)
#pragma unroll
        for (int fn = 0; fn < 4; fn++)
#pragma unroll
            for (int e = 0; e < 4; e++) acc[fm][fn][e] = 0.0f;

    gemm_core(A, W, N, m0, n0, threadIdx.x, As, Bs, acc);

    const int tid  = threadIdx.x;
    const int wid  = tid >> 5;
    const int lane = tid & 31;
    const int g    = lane >> 2;
    const int t    = lane & 3;
    const int warp_m = wid >> 2;
    const int warp_n = wid & 3;

#pragma unroll
    for (int fm = 0; fm < 4; fm++) {
        int row = m0 + warp_m * 64 + fm * 16 + g;
        int srow = rowoff + row;
#pragma unroll
        for (int fn = 0; fn < 4; fn++) {
            int col = n0 + warp_n * 32 + fn * 8 + 2 * t;
            float bx0 = bias[col], by0 = bias[col + 1];
            float v0x = acc[fm][fn][0] + bx0, v0y = acc[fm][fn][1] + by0;
            float v1x = acc[fm][fn][2] + bx0, v1y = acc[fm][fn][3] + by0;
            if (qmode) {
                *(uint32_t*)&Qh[(size_t)srow * 1024 + col] =
                    hpack(__float2half(v0x), __float2half(v0y));
                *(uint32_t*)&Qh[(size_t)(srow + 8) * 1024 + col] =
                    hpack(__float2half(v1x), __float2half(v1y));
            } else if (col < 1024) {
                *(uint32_t*)&Kh[(size_t)srow * 1024 + col] =
                    hpack(__float2half(v0x), __float2half(v0y));
                *(uint32_t*)&Kh[(size_t)(srow + 8) * 1024 + col] =
                    hpack(__float2half(v1x), __float2half(v1y));
            } else {
                int d0 = col - 1024;
                __half h0, l0, h1, l1, h2, l2, h3, l3;
                hsplit(v0x, h0, l0); hsplit(v0y, h1, l1);
                hsplit(v1x, h2, l2); hsplit(v1y, h3, l3);
                VThi[(size_t)d0 * 4096 + srow] = h0;        VTlo[(size_t)d0 * 4096 + srow] = l0;
                VThi[(size_t)(d0 + 1) * 4096 + srow] = h1;  VTlo[(size_t)(d0 + 1) * 4096 + srow] = l1;
                VThi[(size_t)d0 * 4096 + srow + 8] = h2;    VTlo[(size_t)d0 * 4096 + srow + 8] = l2;
                VThi[(size_t)(d0 + 1) * 4096 + srow + 8] = h3; VTlo[(size_t)(d0 + 1) * 4096 + srow + 8] = l3;
            }
        }
    }
}

// Output projection GEMM (fp32 epilogue), same core.
__global__ __launch_bounds__(256) void gemm_proj_kernel(
    const float* __restrict__ A, const float* __restrict__ W,
    const float* __restrict__ bias, float* __restrict__ outf)
{
    __shared__ float smem[GEMM_SMEM_FLOATS];
    float* As = smem;
    float* Bs = smem + 128 * AS_STRIDE;

    const int n0 = blockIdx.x << 7;
    const int m0 = blockIdx.y << 7;

    float acc[4][4][4];
#pragma unroll
    for (int fm = 0; fm < 4; fm++)
#pragma unroll
        for (int fn = 0; fn < 4; fn++)
#pragma unroll
            for (int e = 0; e < 4; e++) acc[fm][fn][e] = 0.0f;

    gemm_core(A, W, 1024, m0, n0, threadIdx.x, As, Bs, acc);

    const int tid  = threadIdx.x;
    const int wid  = tid >> 5;
    const int lane = tid & 31;
    const int g    = lane >> 2;
    const int t    = lane & 3;
    const int warp_m = wid >> 2;
    const int warp_n = wid & 3;

#pragma unroll
    for (int fm = 0; fm < 4; fm++) {
        int row = m0 + warp_m * 64 + fm * 16 + g;
#pragma unroll
        for (int fn = 0; fn < 4; fn++) {
            int col = n0 + warp_n * 32 + fn * 8 + 2 * t;
            float bx0 = bias[col], by0 = bias[col + 1];
            *(float2*)&outf[(size_t)row * 1024 + col] =
                make_float2(acc[fm][fn][0] + bx0, acc[fm][fn][1] + by0);
            *(float2*)&outf[(size_t)(row + 8) * 1024 + col] =
                make_float2(acc[fm][fn][2] + bx0, acc[fm][fn][3] + by0);
        }
    }
}

// ---------------------------------------------------------------------------
// Tensor-core flash attention v6: fp16 datapath.
//   QK^T: plain fp16, 1 mma. PV: P plain fp16, V hi/lo split, 2 mmas.
//   96 mmas/tile/warp vs 192 in v5. Split-KV load balance kept.
// smem: Qh[128][72] + {Kh,Vh,Vl}[2][64][72] fp16 = 73728 B.
// ---------------------------------------------------------------------------
#define BSTR 72   // fp16 row stride (144 B = 36 words; bank = 4*row + t)

__device__ __forceinline__ void load_tile_async(
    int tid, int col0, int s0,
    const __half* __restrict__ Kh_g,
    const __half* __restrict__ VThi_g, const __half* __restrict__ VTlo_g,
    __half* Kh, __half* Vh, __half* Vl)
{
#pragma unroll
    for (int c = 0; c < 2; c++) {
        int idx = (tid << 1) + c;          // 0..511
        int j = idx >> 3;                  // 0..63
        int ch = (idx & 7) << 3;           // fp16 offset, 16B chunks
        cp16(sma(Kh + j * BSTR + ch), Kh_g + (size_t)(s0 + j) * 1024 + col0 + ch);
        cp16(sma(Vh + j * BSTR + ch), VThi_g + (size_t)(col0 + j) * 4096 + s0 + ch);
        cp16(sma(Vl + j * BSTR + ch), VTlo_g + (size_t)(col0 + j) * 4096 + s0 + ch);
    }
}

__global__ __launch_bounds__(256, 2) void attn_mma_kernel(
    const __half* __restrict__ Qh_g, const __half* __restrict__ Kh_g,
    const __half* __restrict__ VThi_g, const __half* __restrict__ VTlo_g)
{
    extern __shared__ char smraw[];
    __half* Qh_s = (__half*)smraw;          // [128][BSTR]
    __half* Kh_s = Qh_s + 128 * BSTR;       // [2][64][BSTR]
    __half* Vh_s = Kh_s + 2 * 64 * BSTR;
    __half* Vl_s = Vh_s + 2 * 64 * BSTR;

    const int tid  = threadIdx.x;
    const int wid  = tid >> 5;
    const int lane = tid & 31;
    const int g    = lane >> 2;   // 0..7
    const int t    = lane & 3;    // 0..3

    const int bx = blockIdx.x;               // 0..31, largest work first
    const int qb = 15 - (bx >> 1);
    const int split = bx & 1;
    const int h  = blockIdx.y;
    const int q0 = qb << 7;
    const int col0 = h * HDIM;

    const int nt_total = 2 * qb + 34;        // 34..64
    const int nt0 = nt_total >> 1;           // 17..32
    const int tb = split ? nt0 : 0;
    const int te = split ? nt_total : nt0;

    const int row0 = wid * 16 + g;

    // ---- prologue: async-load Q + tiles tb, tb+1 ----
#pragma unroll
    for (int c = 0; c < 4; c++) {
        int idx = (tid << 2) + c;          // 0..1023
        int r = idx >> 3;
        int ch = (idx & 7) << 3;
        cp16(sma(Qh_s + r * BSTR + ch), Qh_g + (size_t)(q0 + r) * 1024 + col0 + ch);
    }
    load_tile_async(tid, col0, tb << 6, Kh_g, VThi_g, VTlo_g,
                    Kh_s, Vh_s, Vl_s);
    CP_COMMIT();
    load_tile_async(tid, col0, (tb + 1) << 6, Kh_g, VThi_g, VTlo_g,
                    Kh_s + 64 * BSTR, Vh_s + 64 * BSTR, Vl_s + 64 * BSTR);
    CP_COMMIT();

    float O[8][4];
#pragma unroll
    for (int fn = 0; fn < 8; fn++)
#pragma unroll
        for (int e = 0; e < 4; e++) O[fn][e] = 0.0f;
    float m0 = -INFINITY, m1 = -INFINITY, l0 = 0.0f, l1 = 0.0f;

    for (int tt = tb; tt < te; tt++) {
        int s0 = tt << 6;
        int p = (tt - tb) & 1;
        const __half* Kh = Kh_s + p * 64 * BSTR;
        const __half* Vh = Vh_s + p * 64 * BSTR;
        const __half* Vl = Vl_s + p * 64 * BSTR;

        CP_WAIT1();
        __syncthreads();

        // ---- S = Q K^T: plain fp16, 1 mma per fragment ----
        float sacc[8][4];
#pragma unroll
        for (int fn = 0; fn < 8; fn++)
#pragma unroll
            for (int e = 0; e < 4; e++) sacc[fn][e] = 0.0f;

#pragma unroll
        for (int ks = 0; ks < 4; ks++) {
            int k0 = ks << 4;
            uint32_t a0 = *(uint32_t*)&Qh_s[row0 * BSTR + k0 + 2 * t];
            uint32_t a1 = *(uint32_t*)&Qh_s[(row0 + 8) * BSTR + k0 + 2 * t];
            uint32_t a2 = *(uint32_t*)&Qh_s[row0 * BSTR + k0 + 2 * t + 8];
            uint32_t a3 = *(uint32_t*)&Qh_s[(row0 + 8) * BSTR + k0 + 2 * t + 8];
#pragma unroll
            for (int fn = 0; fn < 8; fn++) {
                int key = fn * 8 + g;
                uint32_t b0 = *(uint32_t*)&Kh[key * BSTR + k0 + 2 * t];
                uint32_t b1 = *(uint32_t*)&Kh[key * BSTR + k0 + 2 * t + 8];
                mma_f16(sacc[fn], a0, a1, a2, a3, b0, b1);
            }
        }

        // ---- scale + mask ----
        const float scale = 0.125f;
        bool bnd = (s0 + 63 >= q0 + 2048);
#pragma unroll
        for (int fn = 0; fn < 8; fn++) {
#pragma unroll
            for (int e = 0; e < 4; e++) {
                float s = sacc[fn][e] * scale;
                if (bnd) {
                    int col = fn * 8 + 2 * t + (e & 1);
                    int rw  = (e < 2) ? row0 : row0 + 8;
                    if (s0 + col >= q0 + rw + 2048) s = -1e30f;
                }
                sacc[fn][e] = s;
            }
        }

        // ---- row max (warp-local over t: shfl xor 1,2) ----
        float rm0 = -INFINITY, rm1 = -INFINITY;
#pragma unroll
        for (int fn = 0; fn < 8; fn++) {
            rm0 = fmaxf(rm0, fmaxf(sacc[fn][0], sacc[fn][1]));
            rm1 = fmaxf(rm1, fmaxf(sacc[fn][2], sacc[fn][3]));
        }
        rm0 = fmaxf(rm0, __shfl_xor_sync(0xffffffffu, rm0, 1));
        rm0 = fmaxf(rm0, __shfl_xor_sync(0xffffffffu, rm0, 2));
        rm1 = fmaxf(rm1, __shfl_xor_sync(0xffffffffu, rm1, 1));
        rm1 = fmaxf(rm1, __shfl_xor_sync(0xffffffffu, rm1, 2));

        float mn0 = fmaxf(m0, rm0), mn1 = fmaxf(m1, rm1);
        float a0s = __expf(m0 - mn0), a1s = __expf(m1 - mn1);
        m0 = mn0; m1 = mn1;

        // ---- P = exp(S - m) in place, row sums ----
        float rs0 = 0.0f, rs1 = 0.0f;
#pragma unroll
        for (int fn = 0; fn < 8; fn++) {
            float p0 = __expf(sacc[fn][0] - m0);
            float p1 = __expf(sacc[fn][1] - m0);
            float p2 = __expf(sacc[fn][2] - m1);
            float p3 = __expf(sacc[fn][3] - m1);
            sacc[fn][0] = p0; sacc[fn][1] = p1;
            sacc[fn][2] = p2; sacc[fn][3] = p3;
            rs0 += p0 + p1; rs1 += p2 + p3;
        }
        rs0 += __shfl_xor_sync(0xffffffffu, rs0, 1);
        rs0 += __shfl_xor_sync(0xffffffffu, rs0, 2);
        rs1 += __shfl_xor_sync(0xffffffffu, rs1, 1);
        rs1 += __shfl_xor_sync(0xffffffffu, rs1, 2);
        l0 = l0 * a0s + rs0;
        l1 = l1 * a1s + rs1;

#pragma unroll
        for (int fn = 0; fn < 8; fn++) {
            O[fn][0] *= a0s; O[fn][1] *= a0s;
            O[fn][2] *= a1s; O[fn][3] *= a1s;
        }

        // ---- O += P V: P plain fp16, V hi/lo (2 mmas) ----
#pragma unroll
        for (int ks = 0; ks < 4; ks++) {
            int k0 = ks << 4;
            uint32_t ph0 = hpack(__float2half(sacc[2 * ks][0]),     __float2half(sacc[2 * ks][1]));
            uint32_t ph1 = hpack(__float2half(sacc[2 * ks][2]),     __float2half(sacc[2 * ks][3]));
            uint32_t ph2 = hpack(__float2half(sacc[2 * ks + 1][0]), __float2half(sacc[2 * ks + 1][1]));
            uint32_t ph3 = hpack(__float2half(sacc[2 * ks + 1][2]), __float2half(sacc[2 * ks + 1][3]));
#pragma unroll
            for (int fn = 0; fn < 8; fn++) {
                int dd = fn * 8 + g;
                uint32_t vh0 = *(uint32_t*)&Vh[dd * BSTR + k0 + 2 * t];
                uint32_t vh1 = *(uint32_t*)&Vh[dd * BSTR + k0 + 2 * t + 8];
                uint32_t vl0 = *(uint32_t*)&Vl[dd * BSTR + k0 + 2 * t];
                uint32_t vl1 = *(uint32_t*)&Vl[dd * BSTR + k0 + 2 * t + 8];
                mma_f16(O[fn], ph0, ph1, ph2, ph3, vh0, vh1);
                mma_f16(O[fn], ph0, ph1, ph2, ph3, vl0, vl1);
            }
        }

        __syncthreads();   // all warps done reading buffer p
        int nt = tt + 2;
        if (nt < te) {
            load_tile_async(tid, col0, nt << 6, Kh_g, VThi_g, VTlo_g,
                            Kh_s + p * 64 * BSTR, Vh_s + p * 64 * BSTR, Vl_s + p * 64 * BSTR);
        }
        CP_COMMIT();   // keep group numbering aligned even when empty
    }

    // ---- store unnormalized partial O + (m, l) ----
#pragma unroll
    for (int fn = 0; fn < 8; fn++) {
        int col = fn * 8 + 2 * t;
        *(float2*)&g_Op[split][h][qb][row0][col]     = make_float2(O[fn][0], O[fn][1]);
        *(float2*)&g_Op[split][h][qb][row0 + 8][col] = make_float2(O[fn][2], O[fn][3]);
    }
    if (t == 0) {
        g_ml[split][h][qb][0][row0] = m0;     g_ml[split][h][qb][1][row0] = l0;
        g_ml[split][h][qb][0][row0 + 8] = m1; g_ml[split][h][qb][1][row0 + 8] = l1;
    }
}

// ---------------------------------------------------------------------------
// Combine the two key-split halves: Y = (e0*O0 + e1*O1) / (e0*l0 + e1*l1)
// ---------------------------------------------------------------------------
__global__ __launch_bounds__(256) void attn_combine_kernel(float* __restrict__ Y)
{
    int qb = blockIdx.x, h = blockIdx.y;
    int tid = threadIdx.x;
    int row = tid >> 1;            // 0..127
    int c0 = (tid & 1) << 5;       // 0 or 32

    float m0 = g_ml[0][h][qb][0][row], l0 = g_ml[0][h][qb][1][row];
    float m1 = g_ml[1][h][qb][0][row], l1 = g_ml[1][h][qb][1][row];
    float M = fmaxf(m0, m1);
    float e0 = __expf(m0 - M), e1 = __expf(m1 - M);
    float inv = 1.0f / (e0 * l0 + e1 * l1);
    float s0 = e0 * inv, s1 = e1 * inv;

    const float* O0 = &g_Op[0][h][qb][row][c0];
    const float* O1 = &g_Op[1][h][qb][row][c0];
    float* y = &Y[(size_t)((qb << 7) + row) * D_MOD + h * HDIM + c0];
#pragma unroll
    for (int c = 0; c < 32; c += 4) {
        float4 a = *(const float4*)&O0[c];
        float4 b = *(const float4*)&O1[c];
        float4 r;
        r.x = a.x * s0 + b.x * s1;
        r.y = a.y * s0 + b.y * s1;
        r.z = a.z * s0 + b.z * s1;
        r.w = a.w * s0 + b.w * s1;
        *(float4*)&y[c] = r;
    }
}

// ---------------------------------------------------------------------------
extern "C" void kernel_launch(void* const* d_in, const int* in_sizes, int n_in,
                              void* d_out, int out_size)
{
    (void)in_sizes; (void)n_in; (void)out_size;
    const float* l        = (const float*)d_in[0];
    const float* x        = (const float*)d_in[1];
    const float* W_attn_l = (const float*)d_in[2];
    const float* b_attn_l = (const float*)d_in[3];
    const float* W_attn_c = (const float*)d_in[4];
    const float* b_attn_c = (const float*)d_in[5];
    const float* W_q      = (const float*)d_in[6];
    const float* b_q      = (const float*)d_in[7];
    const float* W_proj   = (const float*)d_in[8];
    const float* b_proj   = (const float*)d_in[9];
    float* out = (float*)d_out;

    __half *Kh, *Qh, *VThi, *VTlo;
    float* Yp;
    cudaGetSymbolAddress((void**)&Kh, g_Kh);
    cudaGetSymbolAddress((void**)&Qh, g_Qh);
    cudaGetSymbolAddress((void**)&VThi, g_VThi);
    cudaGetSymbolAddress((void**)&VTlo, g_VTlo);
    cudaGetSymbolAddress((void**)&Yp, g_Y);

    dim3 blk(256);

    // merged QKV projections: one launch, grid (40, 16)
    gemm_qkv_kernel<<<dim3(40, 16), blk>>>(l, x,
        W_attn_l, b_attn_l, W_attn_c, b_attn_c, W_q, b_q,
        Kh, Qh, VThi, VTlo);

    // attention: 32 (qb-desc, split) x 16 heads; smem = 73728 B (2 CTA/SM)
    size_t smem = (size_t)(128 + 6 * 64) * BSTR * sizeof(__half);
    cudaFuncSetAttribute(attn_mma_kernel, cudaFuncAttributeMaxDynamicSharedMemorySize, (int)smem);
    attn_mma_kernel<<<dim3(32, 16), blk, smem>>>(Qh, Kh, VThi, VTlo);

    // combine split halves -> Y
    attn_combine_kernel<<<dim3(16, 16), blk>>>(Yp);

    // output projection
    gemm_proj_kernel<<<dim3(8, 16), blk>>>(Yp, W_proj, b_proj, out);
}

// round 17
// speedup vs baseline: 2.0196x; 1.3494x over previous
#include <cuda_runtime.h>
#include <cuda_fp16.h>
#include <math.h>
#include <stdint.h>

// Problem constants: B=1, T=2048, D=1024, H=16, HD=64
#define T_SEQ 2048
#define D_MOD 1024
#define NH    16
#define HDIM  64

// Scratch (allocation-free rule: __device__ globals)
__device__ __half g_lh[2048 * 1024];    // l in fp16
__device__ __half g_xh[2048 * 1024];    // x in fp16
__device__ __half g_WTl[2048 * 1024];   // W_attn_l^T [n][k] fp16
__device__ __half g_WTc[2048 * 1024];   // W_attn_c^T
__device__ __half g_WTq[1024 * 1024];   // W_q^T
__device__ __half g_WTp[1024 * 1024];   // W_proj^T
__device__ __half g_Kh[4096 * 1024];    // K natural [s][1024], fp16
__device__ __half g_Qh[2048 * 1024];    // Q natural [q][1024], fp16
__device__ __half g_VThi[1024 * 4096];  // V transposed [d][4096], fp16 hi
__device__ __half g_VTlo[1024 * 4096];  // fp16 lo (v - hi)
__device__ __half g_Yh[2048 * 1024];    // attention output fp16 (proj input)
// split-KV partials
__device__ float g_Op[2][NH][16][128][64];
__device__ float g_ml[2][NH][16][2][128];

// ---------------------------------------------------------------------------
// helpers
// ---------------------------------------------------------------------------
__device__ __forceinline__ void mma_f16(float* c,
    uint32_t a0, uint32_t a1, uint32_t a2, uint32_t a3,
    uint32_t b0, uint32_t b1)
{
    asm volatile(
        "mma.sync.aligned.m16n8k16.row.col.f32.f16.f16.f32 "
        "{%0,%1,%2,%3}, {%4,%5,%6,%7}, {%8,%9}, {%0,%1,%2,%3};\n"
        : "+f"(c[0]), "+f"(c[1]), "+f"(c[2]), "+f"(c[3])
        : "r"(a0), "r"(a1), "r"(a2), "r"(a3), "r"(b0), "r"(b1));
}

__device__ __forceinline__ void hsplit(float x, __half& h, __half& l) {
    h = __float2half(x);
    l = __float2half(x - __half2float(h));
}

__device__ __forceinline__ uint32_t hpack(__half lo, __half hi) {
    __half2 p = __halves2half2(lo, hi);   // lo -> bits[0:16)
    return *(uint32_t*)&p;
}

__device__ __forceinline__ void cp16(uint32_t dst, const void* src) {
    asm volatile("cp.async.cg.shared.global [%0], [%1], 16;\n" :: "r"(dst), "l"(src));
}
#define CP_COMMIT() asm volatile("cp.async.commit_group;\n" ::: "memory")
#define CP_WAIT1()  asm volatile("cp.async.wait_group 1;\n" ::: "memory")

__device__ __forceinline__ uint32_t sma(const void* p) {
    return (uint32_t)__cvta_generic_to_shared(p);
}

// ---------------------------------------------------------------------------
// Pre-pass 1: convert l, x to fp16
// ---------------------------------------------------------------------------
__global__ __launch_bounds__(256) void cvt_inputs_kernel(
    const float* __restrict__ l, const float* __restrict__ x,
    __half* __restrict__ lh, __half* __restrict__ xh)
{
    int j = blockIdx.x * 256 + threadIdx.x;     // 0..524287 float4 per tensor
    float4 a = ((const float4*)l)[j];
    ((uint2*)lh)[j] = make_uint2(hpack(__float2half(a.x), __float2half(a.y)),
                                 hpack(__float2half(a.z), __float2half(a.w)));
    float4 b = ((const float4*)x)[j];
    ((uint2*)xh)[j] = make_uint2(hpack(__float2half(b.x), __float2half(b.y)),
                                 hpack(__float2half(b.z), __float2half(b.w)));
}

// ---------------------------------------------------------------------------
// Pre-pass 2: transpose W [1024][N] fp32 -> WT [N][1024] fp16.
// grid (32, 16, 4): z selects which W; 64x64 tiles.
// ---------------------------------------------------------------------------
__global__ __launch_bounds__(256) void transpose_w_kernel(
    const float* __restrict__ Wl, const float* __restrict__ Wc,
    const float* __restrict__ Wq, const float* __restrict__ Wp,
    __half* __restrict__ WTl, __half* __restrict__ WTc,
    __half* __restrict__ WTq, __half* __restrict__ WTp)
{
    const float* W; __half* WT; int N;
    switch (blockIdx.z) {
        case 0: W = Wl; WT = WTl; N = 2048; break;
        case 1: W = Wc; WT = WTc; N = 2048; break;
        case 2: W = Wq; WT = WTq; N = 1024; break;
        default: W = Wp; WT = WTp; N = 1024; break;
    }
    int n0 = blockIdx.x << 6;
    if (n0 >= N) return;
    int k0 = blockIdx.y << 6;

    __shared__ float ts[64][65];
    int tid = threadIdx.x;
#pragma unroll
    for (int i = 0; i < 4; i++) {
        int idx = tid + (i << 8);          // 0..1023 float4 slots
        int r = idx >> 4;                  // k row 0..63
        int c4 = (idx & 15) << 2;          // n col
        float4 v = *(const float4*)&W[(size_t)(k0 + r) * N + n0 + c4];
        ts[r][c4] = v.x; ts[r][c4 + 1] = v.y;
        ts[r][c4 + 2] = v.z; ts[r][c4 + 3] = v.w;
    }
    __syncthreads();
#pragma unroll
    for (int i = 0; i < 8; i++) {
        int idx = tid + (i << 8);          // 0..2047 word slots
        int n = idx >> 5;                  // 0..63
        int w = idx & 31;                  // k word -> k = 2w
        *(uint32_t*)&WT[(size_t)(n0 + n) * 1024 + k0 + 2 * w] =
            hpack(__float2half(ts[2 * w][n]), __float2half(ts[2 * w + 1][n]));
    }
}

// ---------------------------------------------------------------------------
// fp16 GEMM core: C[128,128] = A[m0:,1024] @ WT[n0:,1024]^T, fp32 accum.
// Mirrors the measured-good attention loop: cp.async double-buffer,
// stride-72 fp16 smem, conflict-free LDS.32 fragment gathers.
// ---------------------------------------------------------------------------
#define GSTR 72   // halves per row (144 B = 36 words; bank = 4*row + t)
#define G16_SMEM (2 * 2 * 128 * GSTR * (int)sizeof(__half))   // 73728 B

__device__ __forceinline__ void g16_load_tile(
    int tid, const __half* __restrict__ Ab, const __half* __restrict__ Bb,
    int k0, __half* As, __half* Bs)
{
#pragma unroll
    for (int c = 0; c < 4; c++) {
        int idx = tid + (c << 8);          // 0..1023
        int r = idx >> 3;                  // 0..127
        int ch = (idx & 7) << 3;           // halves, 16B chunks
        cp16(sma(As + r * GSTR + ch), Ab + (size_t)r * 1024 + k0 + ch);
        cp16(sma(Bs + r * GSTR + ch), Bb + (size_t)r * 1024 + k0 + ch);
    }
}

__device__ __forceinline__ void g16_core(
    const __half* __restrict__ Ab, const __half* __restrict__ Bb,
    int tid, __half* As_s, __half* Bs_s, float acc[4][4][4])
{
    const int lane = tid & 31;
    const int g    = lane >> 2;
    const int t    = lane & 3;
    const int warp_m = (tid >> 5) >> 2;
    const int warp_n = (tid >> 5) & 3;

    g16_load_tile(tid, Ab, Bb, 0, As_s, Bs_s);
    CP_COMMIT();
    g16_load_tile(tid, Ab, Bb, 64, As_s + 128 * GSTR, Bs_s + 128 * GSTR);
    CP_COMMIT();

    for (int kt = 0; kt < 16; kt++) {
        int p = kt & 1;
        const __half* Ap = As_s + p * 128 * GSTR;
        const __half* Bp = Bs_s + p * 128 * GSTR;
        CP_WAIT1();
        __syncthreads();

#pragma unroll
        for (int ks = 0; ks < 4; ks++) {
            int k0 = ks << 4;
            uint32_t b0[4], b1[4];
#pragma unroll
            for (int fn = 0; fn < 4; fn++) {
                int nr = warp_n * 32 + fn * 8 + g;
                b0[fn] = *(uint32_t*)&Bp[nr * GSTR + k0 + 2 * t];
                b1[fn] = *(uint32_t*)&Bp[nr * GSTR + k0 + 2 * t + 8];
            }
#pragma unroll
            for (int fm = 0; fm < 4; fm++) {
                int mr = warp_m * 64 + fm * 16 + g;
                uint32_t a0 = *(uint32_t*)&Ap[mr * GSTR + k0 + 2 * t];
                uint32_t a1 = *(uint32_t*)&Ap[(mr + 8) * GSTR + k0 + 2 * t];
                uint32_t a2 = *(uint32_t*)&Ap[mr * GSTR + k0 + 2 * t + 8];
                uint32_t a3 = *(uint32_t*)&Ap[(mr + 8) * GSTR + k0 + 2 * t + 8];
#pragma unroll
                for (int fn = 0; fn < 4; fn++)
                    mma_f16(acc[fm][fn], a0, a1, a2, a3, b0[fn], b1[fn]);
            }
        }
        __syncthreads();
        int nk = kt + 2;
        if (nk < 16)
            g16_load_tile(tid, Ab, Bb, nk << 6,
                          As_s + p * 128 * GSTR, Bs_s + p * 128 * GSTR);
        CP_COMMIT();
    }
}

// ---------------------------------------------------------------------------
// Merged QKV projection GEMM: grid (40, 16). fp16 in/out.
// ---------------------------------------------------------------------------
__global__ __launch_bounds__(256) void gemm_qkv_kernel(
    const __half* __restrict__ lh, const __half* __restrict__ xh,
    const __half* __restrict__ WTl, const __half* __restrict__ WTc,
    const __half* __restrict__ WTq,
    const float* __restrict__ bl, const float* __restrict__ bc2,
    const float* __restrict__ bq,
    __half* __restrict__ Kh, __half* __restrict__ Qh,
    __half* __restrict__ VThi, __half* __restrict__ VTlo)
{
    extern __shared__ __half gsm[];
    __half* As_s = gsm;                  // [2][128][GSTR]
    __half* Bs_s = gsm + 2 * 128 * GSTR;

    const int bx = blockIdx.x;
    const __half *Ag, *Bg;
    const float* bias;
    int rowoff, n0;
    bool qmode;
    if (bx < 16)      { Ag = lh; Bg = WTl; bias = bl;  rowoff = 0;    n0 = bx << 7;        qmode = false; }
    else if (bx < 32) { Ag = xh; Bg = WTc; bias = bc2; rowoff = 2048; n0 = (bx - 16) << 7; qmode = false; }
    else              { Ag = xh; Bg = WTq; bias = bq;  rowoff = 0;    n0 = (bx - 32) << 7; qmode = true;  }
    const int m0 = blockIdx.y << 7;

    float acc[4][4][4];
#pragma unroll
    for (int fm = 0; fm < 4; fm++)
#pragma unroll
        for (int fn = 0; fn < 4; fn++)
#pragma unroll
            for (int e = 0; e < 4; e++) acc[fm][fn][e] = 0.0f;

    g16_core(Ag + (size_t)m0 * 1024, Bg + (size_t)n0 * 1024,
             threadIdx.x, As_s, Bs_s, acc);

    const int tid  = threadIdx.x;
    const int lane = tid & 31;
    const int g    = lane >> 2;
    const int t    = lane & 3;
    const int warp_m = (tid >> 5) >> 2;
    const int warp_n = (tid >> 5) & 3;

#pragma unroll
    for (int fm = 0; fm < 4; fm++) {
        int row = m0 + warp_m * 64 + fm * 16 + g;
        int srow = rowoff + row;
#pragma unroll
        for (int fn = 0; fn < 4; fn++) {
            int col = n0 + warp_n * 32 + fn * 8 + 2 * t;
            float bx0 = bias[col], by0 = bias[col + 1];
            float v0x = acc[fm][fn][0] + bx0, v0y = acc[fm][fn][1] + by0;
            float v1x = acc[fm][fn][2] + bx0, v1y = acc[fm][fn][3] + by0;
            if (qmode) {
                *(uint32_t*)&Qh[(size_t)srow * 1024 + col] =
                    hpack(__float2half(v0x), __float2half(v0y));
                *(uint32_t*)&Qh[(size_t)(srow + 8) * 1024 + col] =
                    hpack(__float2half(v1x), __float2half(v1y));
            } else if (col < 1024) {
                *(uint32_t*)&Kh[(size_t)srow * 1024 + col] =
                    hpack(__float2half(v0x), __float2half(v0y));
                *(uint32_t*)&Kh[(size_t)(srow + 8) * 1024 + col] =
                    hpack(__float2half(v1x), __float2half(v1y));
            } else {
                int d0 = col - 1024;
                __half h0, l0, h1, l1, h2, l2, h3, l3;
                hsplit(v0x, h0, l0); hsplit(v0y, h1, l1);
                hsplit(v1x, h2, l2); hsplit(v1y, h3, l3);
                VThi[(size_t)d0 * 4096 + srow] = h0;        VTlo[(size_t)d0 * 4096 + srow] = l0;
                VThi[(size_t)(d0 + 1) * 4096 + srow] = h1;  VTlo[(size_t)(d0 + 1) * 4096 + srow] = l1;
                VThi[(size_t)d0 * 4096 + srow + 8] = h2;    VTlo[(size_t)d0 * 4096 + srow + 8] = l2;
                VThi[(size_t)(d0 + 1) * 4096 + srow + 8] = h3; VTlo[(size_t)(d0 + 1) * 4096 + srow + 8] = l3;
            }
        }
    }
}

// Output projection GEMM: A = Yh fp16, B = WTp fp16, fp32 epilogue.
__global__ __launch_bounds__(256) void gemm_proj_kernel(
    const __half* __restrict__ Yh, const __half* __restrict__ WTp,
    const float* __restrict__ bias, float* __restrict__ outf)
{
    extern __shared__ __half gsm[];
    __half* As_s = gsm;
    __half* Bs_s = gsm + 2 * 128 * GSTR;

    const int n0 = blockIdx.x << 7;
    const int m0 = blockIdx.y << 7;

    float acc[4][4][4];
#pragma unroll
    for (int fm = 0; fm < 4; fm++)
#pragma unroll
        for (int fn = 0; fn < 4; fn++)
#pragma unroll
            for (int e = 0; e < 4; e++) acc[fm][fn][e] = 0.0f;

    g16_core(Yh + (size_t)m0 * 1024, WTp + (size_t)n0 * 1024,
             threadIdx.x, As_s, Bs_s, acc);

    const int tid  = threadIdx.x;
    const int lane = tid & 31;
    const int g    = lane >> 2;
    const int t    = lane & 3;
    const int warp_m = (tid >> 5) >> 2;
    const int warp_n = (tid >> 5) & 3;

#pragma unroll
    for (int fm = 0; fm < 4; fm++) {
        int row = m0 + warp_m * 64 + fm * 16 + g;
#pragma unroll
        for (int fn = 0; fn < 4; fn++) {
            int col = n0 + warp_n * 32 + fn * 8 + 2 * t;
            float bx0 = bias[col], by0 = bias[col + 1];
            *(float2*)&outf[(size_t)row * 1024 + col] =
                make_float2(acc[fm][fn][0] + bx0, acc[fm][fn][1] + by0);
            *(float2*)&outf[(size_t)(row + 8) * 1024 + col] =
                make_float2(acc[fm][fn][2] + bx0, acc[fm][fn][3] + by0);
        }
    }
}

// ---------------------------------------------------------------------------
// Tensor-core flash attention v6 (unchanged, measured-good R16): fp16,
// split-KV, cp.async double-buffer.
// ---------------------------------------------------------------------------
#define BSTR 72

__device__ __forceinline__ void load_tile_async(
    int tid, int col0, int s0,
    const __half* __restrict__ Kh_g,
    const __half* __restrict__ VThi_g, const __half* __restrict__ VTlo_g,
    __half* Kh, __half* Vh, __half* Vl)
{
#pragma unroll
    for (int c = 0; c < 2; c++) {
        int idx = (tid << 1) + c;          // 0..511
        int j = idx >> 3;                  // 0..63
        int ch = (idx & 7) << 3;
        cp16(sma(Kh + j * BSTR + ch), Kh_g + (size_t)(s0 + j) * 1024 + col0 + ch);
        cp16(sma(Vh + j * BSTR + ch), VThi_g + (size_t)(col0 + j) * 4096 + s0 + ch);
        cp16(sma(Vl + j * BSTR + ch), VTlo_g + (size_t)(col0 + j) * 4096 + s0 + ch);
    }
}

__global__ __launch_bounds__(256, 2) void attn_mma_kernel(
    const __half* __restrict__ Qh_g, const __half* __restrict__ Kh_g,
    const __half* __restrict__ VThi_g, const __half* __restrict__ VTlo_g)
{
    extern __shared__ char smraw[];
    __half* Qh_s = (__half*)smraw;          // [128][BSTR]
    __half* Kh_s = Qh_s + 128 * BSTR;       // [2][64][BSTR]
    __half* Vh_s = Kh_s + 2 * 64 * BSTR;
    __half* Vl_s = Vh_s + 2 * 64 * BSTR;

    const int tid  = threadIdx.x;
    const int wid  = tid >> 5;
    const int lane = tid & 31;
    const int g    = lane >> 2;
    const int t    = lane & 3;

    const int bx = blockIdx.x;
    const int qb = 15 - (bx >> 1);
    const int split = bx & 1;
    const int h  = blockIdx.y;
    const int q0 = qb << 7;
    const int col0 = h * HDIM;

    const int nt_total = 2 * qb + 34;
    const int nt0 = nt_total >> 1;
    const int tb = split ? nt0 : 0;
    const int te = split ? nt_total : nt0;

    const int row0 = wid * 16 + g;

#pragma unroll
    for (int c = 0; c < 4; c++) {
        int idx = (tid << 2) + c;
        int r = idx >> 3;
        int ch = (idx & 7) << 3;
        cp16(sma(Qh_s + r * BSTR + ch), Qh_g + (size_t)(q0 + r) * 1024 + col0 + ch);
    }
    load_tile_async(tid, col0, tb << 6, Kh_g, VThi_g, VTlo_g,
                    Kh_s, Vh_s, Vl_s);
    CP_COMMIT();
    load_tile_async(tid, col0, (tb + 1) << 6, Kh_g, VThi_g, VTlo_g,
                    Kh_s + 64 * BSTR, Vh_s + 64 * BSTR, Vl_s + 64 * BSTR);
    CP_COMMIT();

    float O[8][4];
#pragma unroll
    for (int fn = 0; fn < 8; fn++)
#pragma unroll
        for (int e = 0; e < 4; e++) O[fn][e] = 0.0f;
    float m0 = -INFINITY, m1 = -INFINITY, l0 = 0.0f, l1 = 0.0f;

    for (int tt = tb; tt < te; tt++) {
        int s0 = tt << 6;
        int p = (tt - tb) & 1;
        const __half* Kh = Kh_s + p * 64 * BSTR;
        const __half* Vh = Vh_s + p * 64 * BSTR;
        const __half* Vl = Vl_s + p * 64 * BSTR;

        CP_WAIT1();
        __syncthreads();

        float sacc[8][4];
#pragma unroll
        for (int fn = 0; fn < 8; fn++)
#pragma unroll
            for (int e = 0; e < 4; e++) sacc[fn][e] = 0.0f;

#pragma unroll
        for (int ks = 0; ks < 4; ks++) {
            int k0 = ks << 4;
            uint32_t a0 = *(uint32_t*)&Qh_s[row0 * BSTR + k0 + 2 * t];
            uint32_t a1 = *(uint32_t*)&Qh_s[(row0 + 8) * BSTR + k0 + 2 * t];
            uint32_t a2 = *(uint32_t*)&Qh_s[row0 * BSTR + k0 + 2 * t + 8];
            uint32_t a3 = *(uint32_t*)&Qh_s[(row0 + 8) * BSTR + k0 + 2 * t + 8];
#pragma unroll
            for (int fn = 0; fn < 8; fn++) {
                int key = fn * 8 + g;
                uint32_t b0 = *(uint32_t*)&Kh[key * BSTR + k0 + 2 * t];
                uint32_t b1 = *(uint32_t*)&Kh[key * BSTR + k0 + 2 * t + 8];
                mma_f16(sacc[fn], a0, a1, a2, a3, b0, b1);
            }
        }

        const float scale = 0.125f;
        bool bnd = (s0 + 63 >= q0 + 2048);
#pragma unroll
        for (int fn = 0; fn < 8; fn++) {
#pragma unroll
            for (int e = 0; e < 4; e++) {
                float s = sacc[fn][e] * scale;
                if (bnd) {
                    int col = fn * 8 + 2 * t + (e & 1);
                    int rw  = (e < 2) ? row0 : row0 + 8;
                    if (s0 + col >= q0 + rw + 2048) s = -1e30f;
                }
                sacc[fn][e] = s;
            }
        }

        float rm0 = -INFINITY, rm1 = -INFINITY;
#pragma unroll
        for (int fn = 0; fn < 8; fn++) {
            rm0 = fmaxf(rm0, fmaxf(sacc[fn][0], sacc[fn][1]));
            rm1 = fmaxf(rm1, fmaxf(sacc[fn][2], sacc[fn][3]));
        }
        rm0 = fmaxf(rm0, __shfl_xor_sync(0xffffffffu, rm0, 1));
        rm0 = fmaxf(rm0, __shfl_xor_sync(0xffffffffu, rm0, 2));
        rm1 = fmaxf(rm1, __shfl_xor_sync(0xffffffffu, rm1, 1));
        rm1 = fmaxf(rm1, __shfl_xor_sync(0xffffffffu, rm1, 2));

        float mn0 = fmaxf(m0, rm0), mn1 = fmaxf(m1, rm1);
        float a0s = __expf(m0 - mn0), a1s = __expf(m1 - mn1);
        m0 = mn0; m1 = mn1;

        float rs0 = 0.0f, rs1 = 0.0f;
#pragma unroll
        for (int fn = 0; fn < 8; fn++) {
            float p0 = __expf(sacc[fn][0] - m0);
            float p1 = __expf(sacc[fn][1] - m0);
            float p2 = __expf(sacc[fn][2] - m1);
            float p3 = __expf(sacc[fn][3] - m1);
            sacc[fn][0] = p0; sacc[fn][1] = p1;
            sacc[fn][2] = p2; sacc[fn][3] = p3;
            rs0 += p0 + p1; rs1 += p2 + p3;
        }
        rs0 += __shfl_xor_sync(0xffffffffu, rs0, 1);
        rs0 += __shfl_xor_sync(0xffffffffu, rs0, 2);
        rs1 += __shfl_xor_sync(0xffffffffu, rs1, 1);
        rs1 += __shfl_xor_sync(0xffffffffu, rs1, 2);
        l0 = l0 * a0s + rs0;
        l1 = l1 * a1s + rs1;

#pragma unroll
        for (int fn = 0; fn < 8; fn++) {
            O[fn][0] *= a0s; O[fn][1] *= a0s;
            O[fn][2] *= a1s; O[fn][3] *= a1s;
        }

#pragma unroll
        for (int ks = 0; ks < 4; ks++) {
            int k0 = ks << 4;
            uint32_t ph0 = hpack(__float2half(sacc[2 * ks][0]),     __float2half(sacc[2 * ks][1]));
            uint32_t ph1 = hpack(__float2half(sacc[2 * ks][2]),     __float2half(sacc[2 * ks][3]));
            uint32_t ph2 = hpack(__float2half(sacc[2 * ks + 1][0]), __float2half(sacc[2 * ks + 1][1]));
            uint32_t ph3 = hpack(__float2half(sacc[2 * ks + 1][2]), __float2half(sacc[2 * ks + 1][3]));
#pragma unroll
            for (int fn = 0; fn < 8; fn++) {
                int dd = fn * 8 + g;
                uint32_t vh0 = *(uint32_t*)&Vh[dd * BSTR + k0 + 2 * t];
                uint32_t vh1 = *(uint32_t*)&Vh[dd * BSTR + k0 + 2 * t + 8];
                uint32_t vl0 = *(uint32_t*)&Vl[dd * BSTR + k0 + 2 * t];
                uint32_t vl1 = *(uint32_t*)&Vl[dd * BSTR + k0 + 2 * t + 8];
                mma_f16(O[fn], ph0, ph1, ph2, ph3, vh0, vh1);
                mma_f16(O[fn], ph0, ph1, ph2, ph3, vl0, vl1);
            }
        }

        __syncthreads();
        int nt = tt + 2;
        if (nt < te) {
            load_tile_async(tid, col0, nt << 6, Kh_g, VThi_g, VTlo_g,
                            Kh_s + p * 64 * BSTR, Vh_s + p * 64 * BSTR, Vl_s + p * 64 * BSTR);
        }
        CP_COMMIT();
    }

#pragma unroll
    for (int fn = 0; fn < 8; fn++) {
        int col = fn * 8 + 2 * t;
        *(float2*)&g_Op[split][h][qb][row0][col]     = make_float2(O[fn][0], O[fn][1]);
        *(float2*)&g_Op[split][h][qb][row0 + 8][col] = make_float2(O[fn][2], O[fn][3]);
    }
    if (t == 0) {
        g_ml[split][h][qb][0][row0] = m0;     g_ml[split][h][qb][1][row0] = l0;
        g_ml[split][h][qb][0][row0 + 8] = m1; g_ml[split][h][qb][1][row0 + 8] = l1;
    }
}

// ---------------------------------------------------------------------------
// Combine split halves; emit fp16 Yh (proj GEMM input).
// ---------------------------------------------------------------------------
__global__ __launch_bounds__(256) void attn_combine_kernel(__half* __restrict__ Yh)
{
    int qb = blockIdx.x, h = blockIdx.y;
    int tid = threadIdx.x;
    int row = tid >> 1;
    int c0 = (tid & 1) << 5;

    float m0 = g_ml[0][h][qb][0][row], l0 = g_ml[0][h][qb][1][row];
    float m1 = g_ml[1][h][qb][0][row], l1 = g_ml[1][h][qb][1][row];
    float M = fmaxf(m0, m1);
    float e0 = __expf(m0 - M), e1 = __expf(m1 - M);
    float inv = 1.0f / (e0 * l0 + e1 * l1);
    float s0 = e0 * inv, s1 = e1 * inv;

    const float* O0 = &g_Op[0][h][qb][row][c0];
    const float* O1 = &g_Op[1][h][qb][row][c0];
    __half* y = &Yh[(size_t)((qb << 7) + row) * D_MOD + h * HDIM + c0];
#pragma unroll
    for (int c = 0; c < 32; c += 4) {
        float4 a = *(const float4*)&O0[c];
        float4 b = *(const float4*)&O1[c];
        float rx = a.x * s0 + b.x * s1;
        float ry = a.y * s0 + b.y * s1;
        float rz = a.z * s0 + b.z * s1;
        float rw = a.w * s0 + b.w * s1;
        *(uint2*)&y[c] = make_uint2(hpack(__float2half(rx), __float2half(ry)),
                                    hpack(__float2half(rz), __float2half(rw)));
    }
}

// ---------------------------------------------------------------------------
extern "C" void kernel_launch(void* const* d_in, const int* in_sizes, int n_in,
                              void* d_out, int out_size)
{
    (void)in_sizes; (void)n_in; (void)out_size;
    const float* l        = (const float*)d_in[0];
    const float* x        = (const float*)d_in[1];
    const float* W_attn_l = (const float*)d_in[2];
    const float* b_attn_l = (const float*)d_in[3];
    const float* W_attn_c = (const float*)d_in[4];
    const float* b_attn_c = (const float*)d_in[5];
    const float* W_q      = (const float*)d_in[6];
    const float* b_q      = (const float*)d_in[7];
    const float* W_proj   = (const float*)d_in[8];
    const float* b_proj   = (const float*)d_in[9];
    float* out = (float*)d_out;

    __half *lh, *xh, *WTl, *WTc, *WTq, *WTp, *Kh, *Qh, *VThi, *VTlo, *Yh;
    cudaGetSymbolAddress((void**)&lh, g_lh);
    cudaGetSymbolAddress((void**)&xh, g_xh);
    cudaGetSymbolAddress((void**)&WTl, g_WTl);
    cudaGetSymbolAddress((void**)&WTc, g_WTc);
    cudaGetSymbolAddress((void**)&WTq, g_WTq);
    cudaGetSymbolAddress((void**)&WTp, g_WTp);
    cudaGetSymbolAddress((void**)&Kh, g_Kh);
    cudaGetSymbolAddress((void**)&Qh, g_Qh);
    cudaGetSymbolAddress((void**)&VThi, g_VThi);
    cudaGetSymbolAddress((void**)&VTlo, g_VTlo);
    cudaGetSymbolAddress((void**)&Yh, g_Yh);

    dim3 blk(256);

    // pre-pass: fp16 inputs + transposed fp16 weights
    cvt_inputs_kernel<<<dim3(2048), blk>>>(l, x, lh, xh);
    transpose_w_kernel<<<dim3(32, 16, 4), blk>>>(W_attn_l, W_attn_c, W_q, W_proj,
                                                 WTl, WTc, WTq, WTp);

    // merged QKV projections: fp16 core, grid (40, 16)
    cudaFuncSetAttribute(gemm_qkv_kernel, cudaFuncAttributeMaxDynamicSharedMemorySize, G16_SMEM);
    gemm_qkv_kernel<<<dim3(40, 16), blk, G16_SMEM>>>(lh, xh, WTl, WTc, WTq,
        b_attn_l, b_attn_c, b_q, Kh, Qh, VThi, VTlo);

    // attention: 32 (qb-desc, split) x 16 heads; smem = 73728 B
    size_t smem = (size_t)(128 + 6 * 64) * BSTR * sizeof(__half);
    cudaFuncSetAttribute(attn_mma_kernel, cudaFuncAttributeMaxDynamicSharedMemorySize, (int)smem);
    attn_mma_kernel<<<dim3(32, 16), blk, smem>>>(Qh, Kh, VThi, VTlo);

    // combine split halves -> Yh (fp16)
    attn_combine_kernel<<<dim3(16, 16), blk>>>(Yh);

    // output projection (fp16 core, fp32 out)
    cudaFuncSetAttribute(gemm_proj_kernel, cudaFuncAttributeMaxDynamicSharedMemorySize, G16_SMEM);
    gemm_proj_kernel<<<dim3(8, 16), blk, G16_SMEM>>>(Yh, WTp, b_proj, out);
}